// round 13
// baseline (speedup 1.0000x reference)
#include <cuda_runtime.h>
#include <cuda_fp16.h>
#include <cuda_pipeline.h>
#include <mma.h>
#include <math.h>
#include <stdint.h>

using namespace nvcuda;

// Problem constants (B=8192, B_pos=8192, D=1024, T=0.1)
#define B_N 8192
#define D_N 1024

// ---------------- scratch: EXACTLY the proven 384 MB set ----------------
static __device__ __align__(256) float  g_S[(size_t)B_N * B_N];      // 256 MB
static __device__ __align__(256) __half g_genH[(size_t)B_N * D_N];   // 16 MB
static __device__ __align__(256) __half g_genL[(size_t)B_N * D_N];   // 16 MB
static __device__ __align__(256) __half g_posH[(size_t)B_N * D_N];   // 16 MB
static __device__ __align__(256) __half g_posL[(size_t)B_N * D_N];   // 16 MB
static __device__ __align__(256) float g_attr[(size_t)B_N * D_N];    // 32 MB
static __device__ __align__(256) float g_rep[(size_t)B_N * D_N];     // 32 MB
static __device__ float g_gn[B_N];
static __device__ float g_pn[B_N];
static __device__ float g_part[B_N * 4];

// ---------------- reductions (proven) ----------------
__device__ __forceinline__ float warpSum(float v) {
#pragma unroll
    for (int o = 16; o > 0; o >>= 1) v += __shfl_xor_sync(0xffffffffu, v, o);
    return v;
}
__device__ __forceinline__ float warpMax(float v) {
#pragma unroll
    for (int o = 16; o > 0; o >>= 1) v = fmaxf(v, __shfl_xor_sync(0xffffffffu, v, o));
    return v;
}
__device__ float blockSum(float v) {
    __shared__ float s[33];
    int lane = threadIdx.x & 31, w = threadIdx.x >> 5;
    __syncthreads();
    v = warpSum(v);
    if (lane == 0) s[w] = v;
    __syncthreads();
    if (w == 0) {
        float t = (threadIdx.x < (blockDim.x >> 5)) ? s[threadIdx.x] : 0.f;
        t = warpSum(t);
        if (lane == 0) s[32] = t;
    }
    __syncthreads();
    return s[32];
}
__device__ float blockMax(float v) {
    __shared__ float s[33];
    int lane = threadIdx.x & 31, w = threadIdx.x >> 5;
    __syncthreads();
    v = warpMax(v);
    if (lane == 0) s[w] = v;
    __syncthreads();
    if (w == 0) {
        float t = (threadIdx.x < (blockDim.x >> 5)) ? s[threadIdx.x] : -INFINITY;
        t = warpMax(t);
        if (lane == 0) s[32] = t;
    }
    __syncthreads();
    return s[32];
}

// ---------------- K0: fused row norms + fp16 hi/lo plane split (proven) ----------------
__global__ __launch_bounds__(256)
void prep_kernel(const float* __restrict__ gen, const float* __restrict__ pos) {
    int row = blockIdx.x;
    const float* src; __half *H, *L; float* dst;
    if (row < B_N) {
        src = gen + (size_t)row * D_N;
        H = g_genH + (size_t)row * D_N; L = g_genL + (size_t)row * D_N;
        dst = &g_gn[row];
    } else {
        int r = row - B_N;
        src = pos + (size_t)r * D_N;
        H = g_posH + (size_t)r * D_N; L = g_posL + (size_t)r * D_N;
        dst = &g_pn[r];
    }
    float s = 0.f;
    for (int c = threadIdx.x * 4; c < D_N; c += blockDim.x * 4) {
        float4 v = *(const float4*)(src + c);
        s += v.x * v.x + v.y * v.y + v.z * v.z + v.w * v.w;
        __half hx = __float2half(v.x), hy = __float2half(v.y);
        __half hz = __float2half(v.z), hw = __float2half(v.w);
        *(__half2*)(H + c)     = __halves2half2(hx, hy);
        *(__half2*)(H + c + 2) = __halves2half2(hz, hw);
        *(__half2*)(L + c)     = __halves2half2(__float2half(v.x - __half2float(hx)),
                                                __float2half(v.y - __half2float(hy)));
        *(__half2*)(L + c + 2) = __halves2half2(__float2half(v.z - __half2float(hz)),
                                                __float2half(v.w - __half2float(hw)));
    }
    s = blockSum(s);
    if (threadIdx.x == 0) *dst = s;
}

#define LDS32 40                   // padded smem stride in halves (32 + 8)
#define TILE32 (128 * LDS32)       // 5120 halves per operand tile
#define LDSP 136
#define WTILE (128 * LDS32)        // 5120 halves
#define PTILE (32 * LDSP)          // 4352 halves

#define SC3_SMEM (3 * 2 * TILE32 * 2)           // 61,440 B
#define WV3_SMEM (3 * (WTILE + PTILE) * 2)      // 56,832 B

// ---------------- score epilogue (shared by both variants) ----------------
__device__ __forceinline__ void score_epilogue(
    wmma::fragment<wmma::accumulator, 16, 16, 16, float> cfr[4][4],
    float* patchbase, int b_is_gen, int m0, int n0, int wm, int wn, int lane, int wid)
{
    float* patch = patchbase + wid * 256;
    const float* bnp = b_is_gen ? g_gn : g_pn;
#pragma unroll
    for (int i = 0; i < 4; i++) {
#pragma unroll
        for (int j = 0; j < 4; j++) {
            wmma::store_matrix_sync(patch, cfr[i][j], 16, wmma::mem_row_major);
            __syncwarp();
            const int pr = lane >> 1, pc = (lane & 1) * 8;
            const int row = m0 + wm + i * 16 + pr;
            const int colb = n0 + wn + j * 16 + pc;
            const float an = g_gn[row];
            float4 bn0 = *(const float4*)(bnp + colb);
            float4 bn1 = *(const float4*)(bnp + colb + 4);
            const float* p = patch + pr * 16 + pc;
            float bns[8] = {bn0.x, bn0.y, bn0.z, bn0.w, bn1.x, bn1.y, bn1.z, bn1.w};
            float o[8];
#pragma unroll
            for (int e = 0; e < 8; e++) {
                float d2 = fmaxf(an + bns[e] - 2.f * p[e], 0.f);
                o[e] = -10.f * sqrtf(d2);
            }
            float* dst = g_S + (size_t)row * B_N + colb;
            *(float4*)dst       = make_float4(o[0], o[1], o[2], o[3]);
            *(float4*)(dst + 4) = make_float4(o[4], o[5], o[6], o[7]);
            __syncwarp();
        }
    }
}

// ---------------- wavg epilogue (shared) ----------------
__device__ __forceinline__ void wavg_epilogue(
    wmma::fragment<wmma::accumulator, 16, 16, 16, float> cfr[4][4],
    float* patchbase, const float* sub, float* outp,
    int m0, int n0, int w_m, int w_nn, int lane, int wid)
{
    float* patch = patchbase + wid * 256;
#pragma unroll
    for (int i = 0; i < 4; i++) {
#pragma unroll
        for (int j = 0; j < 4; j++) {
            wmma::store_matrix_sync(patch, cfr[i][j], 16, wmma::mem_col_major);
            __syncwarp();
            const int pr = lane >> 1, pc = (lane & 1) * 8;
            const int m  = m0 + w_m + j * 16 + pr;
            const int nn = n0 + w_nn + i * 16 + pc;
            const float* p = patch + pr * 16 + pc;
            size_t base = (size_t)m * D_N + nn;
            float4 s0 = *(const float4*)(sub + base);
            float4 s1 = *(const float4*)(sub + base + 4);
            *(float4*)(outp + base)     = make_float4(p[0] - s0.x, p[1] - s0.y,
                                                      p[2] - s0.z, p[3] - s0.w);
            *(float4*)(outp + base + 4) = make_float4(p[4] - s1.x, p[5] - s1.y,
                                                      p[6] - s1.z, p[7] - s1.w);
            __syncwarp();
        }
    }
}

// ================= PRIMARY: 3-stage dynamic-smem variants (1 barrier / k-tile) =================

__global__ __launch_bounds__(128)
void score_wmma3(int b_is_gen) {
    extern __shared__ __align__(32) __half dynsh[];
    const int tid = threadIdx.x, lane = tid & 31, wid = tid >> 5;
    const int wm = (wid & 1) * 64, wn = (wid >> 1) * 64;
    const int m0 = blockIdx.y * 128, n0 = blockIdx.x * 128;

    const __half* segA[3] = { g_genH, g_genH, g_genL };
    const __half* segB[3];
    if (b_is_gen) { segB[0] = g_genH; segB[1] = g_genL; segB[2] = g_genH; }
    else          { segB[0] = g_posH; segB[1] = g_posL; segB[2] = g_posH; }

    const int NTSEG = D_N / 32;          // 32
    const int NTT = 3 * NTSEG;           // 96

    auto issue = [&](int u, int s) {
        int seg = u / NTSEG, t = u - seg * NTSEG;
        const __half* A = segA[seg];
        const __half* B = segB[seg];
        __half* dA = dynsh + s * 2 * TILE32;
        __half* dB = dA + TILE32;
#pragma unroll
        for (int i = 0; i < 4; i++) {
            int f = i * 128 + tid, r = f >> 2, c = f & 3;
            __pipeline_memcpy_async(dA + r * LDS32 + c * 8,
                                    A + (size_t)(m0 + r) * D_N + t * 32 + c * 8, 16);
            __pipeline_memcpy_async(dB + r * LDS32 + c * 8,
                                    B + (size_t)(n0 + r) * D_N + t * 32 + c * 8, 16);
        }
        __pipeline_commit();
    };

    wmma::fragment<wmma::accumulator, 16, 16, 16, float> cfr[4][4];
#pragma unroll
    for (int i = 0; i < 4; i++)
#pragma unroll
        for (int j = 0; j < 4; j++) wmma::fill_fragment(cfr[i][j], 0.f);

    issue(0, 0);
    issue(1, 1);
    for (int u = 0; u < NTT; u++) {
        if (u + 1 < NTT) __pipeline_wait_prior(1);
        else             __pipeline_wait_prior(0);
        __syncthreads();   // data of tile u visible; all warps done reading buf (u+2)%3's previous contents
        if (u + 2 < NTT) issue(u + 2, (u + 2) % 3);
        const __half* bufA = dynsh + (u % 3) * 2 * TILE32;
        const __half* bufB = bufA + TILE32;
#pragma unroll
        for (int ks = 0; ks < 2; ks++) {
            wmma::fragment<wmma::matrix_a, 16, 16, 16, __half, wmma::row_major> afr[4];
            wmma::fragment<wmma::matrix_b, 16, 16, 16, __half, wmma::col_major> bfr[4];
#pragma unroll
            for (int i = 0; i < 4; i++)
                wmma::load_matrix_sync(afr[i], bufA + (wm + i * 16) * LDS32 + ks * 16, LDS32);
#pragma unroll
            for (int j = 0; j < 4; j++)
                wmma::load_matrix_sync(bfr[j], bufB + (wn + j * 16) * LDS32 + ks * 16, LDS32);
#pragma unroll
            for (int i = 0; i < 4; i++)
#pragma unroll
                for (int j = 0; j < 4; j++)
                    wmma::mma_sync(cfr[i][j], afr[i], bfr[j], cfr[i][j]);
        }
    }
    __syncthreads();   // all compute done before smem reused as patch
    score_epilogue(cfr, (float*)dynsh, b_is_gen, m0, n0, wm, wn, lane, wid);
}

__global__ __launch_bounds__(128)
void wavg_wmma3(const float* __restrict__ sub, int to_rep) {
    extern __shared__ __align__(32) __half dynsh[];
    const int tid = threadIdx.x, lane = tid & 31, wid = tid >> 5;
    const int w_nn = (wid & 1) * 64;
    const int w_m  = (wid >> 1) * 64;
    const int n0 = blockIdx.x * 128;
    const int m0 = blockIdx.y * 128;

    const __half* WHp = (const __half*)g_S;
    const __half* WLp = (const __half*)g_S + B_N;
    const __half* segW[3] = { WHp, WHp, WLp };
    const __half* segP[3];
    if (to_rep) { segP[0] = g_genH; segP[1] = g_genL; segP[2] = g_genH; }
    else        { segP[0] = g_posH; segP[1] = g_posL; segP[2] = g_posH; }

    const int NTSEG = B_N / 32;          // 256
    const int NTT = 3 * NTSEG;           // 768

    auto issue = [&](int u, int s) {
        int seg = u / NTSEG, t = u - seg * NTSEG;
        const __half* Wp = segW[seg];
        const __half* Pp = segP[seg];
        __half* dW = dynsh + s * (WTILE + PTILE);
        __half* dP = dW + WTILE;
#pragma unroll
        for (int i = 0; i < 4; i++) {
            int f = i * 128 + tid;
            int rw = f >> 2, cw = f & 3;
            __pipeline_memcpy_async(dW + rw * LDS32 + cw * 8,
                                    Wp + (size_t)(m0 + rw) * (2 * B_N) + t * 32 + cw * 8, 16);
            int rp = f >> 4, cp = f & 15;
            __pipeline_memcpy_async(dP + rp * LDSP + cp * 8,
                                    Pp + (size_t)(t * 32 + rp) * D_N + n0 + cp * 8, 16);
        }
        __pipeline_commit();
    };

    wmma::fragment<wmma::accumulator, 16, 16, 16, float> cfr[4][4];   // [nn][m]
#pragma unroll
    for (int i = 0; i < 4; i++)
#pragma unroll
        for (int j = 0; j < 4; j++) wmma::fill_fragment(cfr[i][j], 0.f);

    issue(0, 0);
    issue(1, 1);
    for (int u = 0; u < NTT; u++) {
        if (u + 1 < NTT) __pipeline_wait_prior(1);
        else             __pipeline_wait_prior(0);
        __syncthreads();
        if (u + 2 < NTT) issue(u + 2, (u + 2) % 3);
        const __half* bufW = dynsh + (u % 3) * (WTILE + PTILE);
        const __half* bufP = bufW + WTILE;
#pragma unroll
        for (int ks = 0; ks < 2; ks++) {
            wmma::fragment<wmma::matrix_a, 16, 16, 16, __half, wmma::col_major> afr[4];
            wmma::fragment<wmma::matrix_b, 16, 16, 16, __half, wmma::col_major> bfr[4];
#pragma unroll
            for (int i = 0; i < 4; i++)
                wmma::load_matrix_sync(afr[i], bufP + (ks * 16) * LDSP + w_nn + i * 16, LDSP);
#pragma unroll
            for (int j = 0; j < 4; j++)
                wmma::load_matrix_sync(bfr[j], bufW + (w_m + j * 16) * LDS32 + ks * 16, LDS32);
#pragma unroll
            for (int i = 0; i < 4; i++)
#pragma unroll
                for (int j = 0; j < 4; j++)
                    wmma::mma_sync(cfr[i][j], afr[i], bfr[j], cfr[i][j]);
        }
    }
    __syncthreads();
    wavg_epilogue(cfr, (float*)dynsh, sub, to_rep ? g_rep : g_attr, m0, n0, w_m, w_nn, lane, wid);
}

// ================= FALLBACK: R12 static 2-stage variants (proven at 5,426 us) =================

__global__ __launch_bounds__(128)
void score_wmma(int b_is_gen) {
    __shared__ __align__(32) __half sh[4 * TILE32];   // 40,960 B
    const int tid = threadIdx.x, lane = tid & 31, wid = tid >> 5;
    const int wm = (wid & 1) * 64, wn = (wid >> 1) * 64;
    const int m0 = blockIdx.y * 128, n0 = blockIdx.x * 128;

    const __half* segA[3] = { g_genH, g_genH, g_genL };
    const __half* segB[3];
    if (b_is_gen) { segB[0] = g_genH; segB[1] = g_genL; segB[2] = g_genH; }
    else          { segB[0] = g_posH; segB[1] = g_posL; segB[2] = g_posH; }

    const int NTSEG = D_N / 32, NTT = 3 * NTSEG;

    auto issue = [&](int u, int s) {
        int seg = u / NTSEG, t = u - seg * NTSEG;
        const __half* A = segA[seg];
        const __half* B = segB[seg];
        __half* dA = sh + s * 2 * TILE32;
        __half* dB = dA + TILE32;
#pragma unroll
        for (int i = 0; i < 4; i++) {
            int f = i * 128 + tid, r = f >> 2, c = f & 3;
            __pipeline_memcpy_async(dA + r * LDS32 + c * 8,
                                    A + (size_t)(m0 + r) * D_N + t * 32 + c * 8, 16);
            __pipeline_memcpy_async(dB + r * LDS32 + c * 8,
                                    B + (size_t)(n0 + r) * D_N + t * 32 + c * 8, 16);
        }
        __pipeline_commit();
    };

    wmma::fragment<wmma::accumulator, 16, 16, 16, float> cfr[4][4];
#pragma unroll
    for (int i = 0; i < 4; i++)
#pragma unroll
        for (int j = 0; j < 4; j++) wmma::fill_fragment(cfr[i][j], 0.f);

    issue(0, 0);
    for (int u = 0; u < NTT; u++) {
        if (u + 1 < NTT) { issue(u + 1, (u + 1) & 1); __pipeline_wait_prior(1); }
        else             { __pipeline_wait_prior(0); }
        __syncthreads();
        const __half* bufA = sh + (u & 1) * 2 * TILE32;
        const __half* bufB = bufA + TILE32;
#pragma unroll
        for (int ks = 0; ks < 2; ks++) {
            wmma::fragment<wmma::matrix_a, 16, 16, 16, __half, wmma::row_major> afr[4];
            wmma::fragment<wmma::matrix_b, 16, 16, 16, __half, wmma::col_major> bfr[4];
#pragma unroll
            for (int i = 0; i < 4; i++)
                wmma::load_matrix_sync(afr[i], bufA + (wm + i * 16) * LDS32 + ks * 16, LDS32);
#pragma unroll
            for (int j = 0; j < 4; j++)
                wmma::load_matrix_sync(bfr[j], bufB + (wn + j * 16) * LDS32 + ks * 16, LDS32);
#pragma unroll
            for (int i = 0; i < 4; i++)
#pragma unroll
                for (int j = 0; j < 4; j++)
                    wmma::mma_sync(cfr[i][j], afr[i], bfr[j], cfr[i][j]);
        }
        __syncthreads();
    }
    score_epilogue(cfr, (float*)sh, b_is_gen, m0, n0, wm, wn, lane, wid);
}

__global__ __launch_bounds__(128)
void wavg_wmma(const float* __restrict__ sub, int to_rep) {
    __shared__ __align__(32) __half shW[2 * WTILE];
    __shared__ __align__(32) __half shP[2 * PTILE];
    const int tid = threadIdx.x, lane = tid & 31, wid = tid >> 5;
    const int w_nn = (wid & 1) * 64;
    const int w_m  = (wid >> 1) * 64;
    const int n0 = blockIdx.x * 128;
    const int m0 = blockIdx.y * 128;

    const __half* WHp = (const __half*)g_S;
    const __half* WLp = (const __half*)g_S + B_N;
    const __half* segW[3] = { WHp, WHp, WLp };
    const __half* segP[3];
    if (to_rep) { segP[0] = g_genH; segP[1] = g_genL; segP[2] = g_genH; }
    else        { segP[0] = g_posH; segP[1] = g_posL; segP[2] = g_posH; }

    const int NTSEG = B_N / 32, NTT = 3 * NTSEG;

    auto issue = [&](int u, int s) {
        int seg = u / NTSEG, t = u - seg * NTSEG;
        const __half* Wp = segW[seg];
        const __half* Pp = segP[seg];
        __half* dW = shW + s * WTILE;
        __half* dP = shP + s * PTILE;
#pragma unroll
        for (int i = 0; i < 4; i++) {
            int f = i * 128 + tid;
            int rw = f >> 2, cw = f & 3;
            __pipeline_memcpy_async(dW + rw * LDS32 + cw * 8,
                                    Wp + (size_t)(m0 + rw) * (2 * B_N) + t * 32 + cw * 8, 16);
            int rp = f >> 4, cp = f & 15;
            __pipeline_memcpy_async(dP + rp * LDSP + cp * 8,
                                    Pp + (size_t)(t * 32 + rp) * D_N + n0 + cp * 8, 16);
        }
        __pipeline_commit();
    };

    wmma::fragment<wmma::accumulator, 16, 16, 16, float> cfr[4][4];
#pragma unroll
    for (int i = 0; i < 4; i++)
#pragma unroll
        for (int j = 0; j < 4; j++) wmma::fill_fragment(cfr[i][j], 0.f);

    issue(0, 0);
    for (int u = 0; u < NTT; u++) {
        if (u + 1 < NTT) { issue(u + 1, (u + 1) & 1); __pipeline_wait_prior(1); }
        else             { __pipeline_wait_prior(0); }
        __syncthreads();
        const __half* bufW = shW + (u & 1) * WTILE;
        const __half* bufP = shP + (u & 1) * PTILE;
#pragma unroll
        for (int ks = 0; ks < 2; ks++) {
            wmma::fragment<wmma::matrix_a, 16, 16, 16, __half, wmma::col_major> afr[4];
            wmma::fragment<wmma::matrix_b, 16, 16, 16, __half, wmma::col_major> bfr[4];
#pragma unroll
            for (int i = 0; i < 4; i++)
                wmma::load_matrix_sync(afr[i], bufP + (ks * 16) * LDSP + w_nn + i * 16, LDSP);
#pragma unroll
            for (int j = 0; j < 4; j++)
                wmma::load_matrix_sync(bfr[j], bufW + (w_m + j * 16) * LDS32 + ks * 16, LDS32);
#pragma unroll
            for (int i = 0; i < 4; i++)
#pragma unroll
                for (int j = 0; j < 4; j++)
                    wmma::mma_sync(cfr[i][j], afr[i], bfr[j], cfr[i][j]);
        }
        __syncthreads();
    }
    wavg_epilogue(cfr, (float*)shW, sub, to_rep ? g_rep : g_attr, m0, n0, w_m, w_nn, lane, wid);
}

// ---------------- softmax + reductions (proven) ----------------
__global__ __launch_bounds__(256)
void softmax_w16(int mask_diag) {
    __shared__ float sm[B_N];
    int row = blockIdx.x;
    const float* Srow = g_S + (size_t)row * B_N;
    float mx = -INFINITY;
    for (int j = threadIdx.x; j < B_N; j += blockDim.x) {
        float v = Srow[j];
        if (mask_diag && j == row) v = -INFINITY;
        sm[j] = v;
        mx = fmaxf(mx, v);
    }
    mx = blockMax(mx);
    float sum = 0.f;
    for (int j = threadIdx.x; j < B_N; j += blockDim.x) {
        float e = expf(sm[j] - mx);
        sm[j] = e;
        sum += e;
    }
    sum = blockSum(sum);
    float inv = 1.f / sum;
    __syncthreads();
    __half* WH = (__half*)g_S + (size_t)row * (2 * B_N);
    __half* WL = WH + B_N;
    for (int j = threadIdx.x; j < B_N; j += blockDim.x) {
        float w = sm[j] * inv;
        __half h = __float2half(w);
        WH[j] = h;
        WL[j] = __float2half(w - __half2float(h));
    }
}

__global__ __launch_bounds__(256)
void row_reduce() {
    int row = blockIdx.x;
    const float* a = g_attr + (size_t)row * D_N;
    const float* r = g_rep + (size_t)row * D_N;
    float sa = 0.f, sr = 0.f, sd = 0.f;
    for (int c = threadIdx.x * 4; c < D_N; c += blockDim.x * 4) {
        float4 av = *(const float4*)(a + c);
        float4 rv = *(const float4*)(r + c);
        float dx = av.x - rv.x, dy = av.y - rv.y, dz = av.z - rv.z, dw = av.w - rv.w;
        sa += av.x * av.x + av.y * av.y + av.z * av.z + av.w * av.w;
        sr += rv.x * rv.x + rv.y * rv.y + rv.z * rv.z + rv.w * rv.w;
        sd += dx * dx + dy * dy + dz * dz + dw * dw;
    }
    sa = blockSum(sa); sr = blockSum(sr); sd = blockSum(sd);
    if (threadIdx.x == 0) {
        g_part[row * 4 + 0] = sd;
        g_part[row * 4 + 1] = sqrtf(sd);
        g_part[row * 4 + 2] = sqrtf(sa);
        g_part[row * 4 + 3] = sqrtf(sr);
    }
}

__global__ __launch_bounds__(256)
void final_reduce(float* __restrict__ out) {
    float s0 = 0.f, s1 = 0.f, s2 = 0.f, s3 = 0.f;
    for (int i = threadIdx.x; i < B_N; i += blockDim.x) {
        s0 += g_part[i * 4 + 0]; s1 += g_part[i * 4 + 1];
        s2 += g_part[i * 4 + 2]; s3 += g_part[i * 4 + 3];
    }
    s0 = blockSum(s0); s1 = blockSum(s1); s2 = blockSum(s2); s3 = blockSum(s3);
    if (threadIdx.x == 0) {
        out[0] = s0 / ((float)B_N * (float)D_N);
        out[1] = s1 / (float)B_N;
        out[2] = s2 / (float)B_N;
        out[3] = s3 / (float)B_N;
    }
}

// ---------------- launch ----------------
extern "C" void kernel_launch(void* const* d_in, const int* in_sizes, int n_in,
                              void* d_out, int out_size) {
    const float* gen = (const float*)d_in[0];
    const float* pos = (const float*)d_in[1];
    float* out = (float*)d_out;

    // Try to enable the 3-stage dynamic-smem variants; fall back to proven static kernels.
    bool big =
        (cudaFuncSetAttribute(score_wmma3, cudaFuncAttributeMaxDynamicSharedMemorySize, SC3_SMEM) == cudaSuccess) &&
        (cudaFuncSetAttribute(wavg_wmma3,  cudaFuncAttributeMaxDynamicSharedMemorySize, WV3_SMEM) == cudaSuccess);

    prep_kernel<<<2 * B_N, 256>>>(gen, pos);

    for (int pass = 0; pass < 2; pass++) {
        // pass 0: attraction (B=pos); pass 1: repulsion (B=gen, diag mask)
        if (big) score_wmma3<<<dim3(64, 64), 128, SC3_SMEM>>>(pass);
        else     score_wmma<<<dim3(64, 64), 128>>>(pass);
        softmax_w16<<<B_N, 256>>>(pass);
        if (big) wavg_wmma3<<<dim3(8, 64), 128, WV3_SMEM>>>(gen, pass);
        else     wavg_wmma<<<dim3(8, 64), 128>>>(gen, pass);
    }

    row_reduce<<<B_N, 256>>>();
    final_reduce<<<1, 256>>>(out);
}

// round 14
// speedup vs baseline: 1.1142x; 1.1142x over previous
#include <cuda_runtime.h>
#include <cuda_fp16.h>
#include <cuda_pipeline.h>
#include <mma.h>
#include <math.h>
#include <stdint.h>

using namespace nvcuda;

// Problem constants (B=8192, B_pos=8192, D=1024, T=0.1)
#define B_N 8192
#define D_N 1024

// ---------------- scratch: EXACTLY the proven 384 MB set ----------------
static __device__ __align__(256) float  g_S[(size_t)B_N * B_N];      // 256 MB
static __device__ __align__(256) __half g_genH[(size_t)B_N * D_N];   // 16 MB
static __device__ __align__(256) __half g_genL[(size_t)B_N * D_N];   // 16 MB
static __device__ __align__(256) __half g_posH[(size_t)B_N * D_N];   // 16 MB
static __device__ __align__(256) __half g_posL[(size_t)B_N * D_N];   // 16 MB
static __device__ __align__(256) float g_attr[(size_t)B_N * D_N];    // 32 MB
static __device__ __align__(256) float g_rep[(size_t)B_N * D_N];     // 32 MB
static __device__ float g_gn[B_N];
static __device__ float g_pn[B_N];
static __device__ float g_part[B_N * 4];

// ---------------- reductions (proven) ----------------
__device__ __forceinline__ float warpSum(float v) {
#pragma unroll
    for (int o = 16; o > 0; o >>= 1) v += __shfl_xor_sync(0xffffffffu, v, o);
    return v;
}
__device__ __forceinline__ float warpMax(float v) {
#pragma unroll
    for (int o = 16; o > 0; o >>= 1) v = fmaxf(v, __shfl_xor_sync(0xffffffffu, v, o));
    return v;
}
__device__ float blockSum(float v) {
    __shared__ float s[33];
    int lane = threadIdx.x & 31, w = threadIdx.x >> 5;
    __syncthreads();
    v = warpSum(v);
    if (lane == 0) s[w] = v;
    __syncthreads();
    if (w == 0) {
        float t = (threadIdx.x < (blockDim.x >> 5)) ? s[threadIdx.x] : 0.f;
        t = warpSum(t);
        if (lane == 0) s[32] = t;
    }
    __syncthreads();
    return s[32];
}
__device__ float blockMax(float v) {
    __shared__ float s[33];
    int lane = threadIdx.x & 31, w = threadIdx.x >> 5;
    __syncthreads();
    v = warpMax(v);
    if (lane == 0) s[w] = v;
    __syncthreads();
    if (w == 0) {
        float t = (threadIdx.x < (blockDim.x >> 5)) ? s[threadIdx.x] : -INFINITY;
        t = warpMax(t);
        if (lane == 0) s[32] = t;
    }
    __syncthreads();
    return s[32];
}

// ---------------- K0: fused row norms + fp16 hi/lo plane split (proven) ----------------
__global__ __launch_bounds__(256)
void prep_kernel(const float* __restrict__ gen, const float* __restrict__ pos) {
    int row = blockIdx.x;
    const float* src; __half *H, *L; float* dst;
    if (row < B_N) {
        src = gen + (size_t)row * D_N;
        H = g_genH + (size_t)row * D_N; L = g_genL + (size_t)row * D_N;
        dst = &g_gn[row];
    } else {
        int r = row - B_N;
        src = pos + (size_t)r * D_N;
        H = g_posH + (size_t)r * D_N; L = g_posL + (size_t)r * D_N;
        dst = &g_pn[r];
    }
    float s = 0.f;
    for (int c = threadIdx.x * 4; c < D_N; c += blockDim.x * 4) {
        float4 v = *(const float4*)(src + c);
        s += v.x * v.x + v.y * v.y + v.z * v.z + v.w * v.w;
        __half hx = __float2half(v.x), hy = __float2half(v.y);
        __half hz = __float2half(v.z), hw = __float2half(v.w);
        *(__half2*)(H + c)     = __halves2half2(hx, hy);
        *(__half2*)(H + c + 2) = __halves2half2(hz, hw);
        *(__half2*)(L + c)     = __halves2half2(__float2half(v.x - __half2float(hx)),
                                                __float2half(v.y - __half2float(hy)));
        *(__half2*)(L + c + 2) = __halves2half2(__float2half(v.z - __half2float(hz)),
                                                __float2half(v.w - __half2float(hw)));
    }
    s = blockSum(s);
    if (threadIdx.x == 0) *dst = s;
}

#define LDS32 40                   // padded smem stride in halves (32 + 8)
#define TILE32 (128 * LDS32)       // 5120 halves per operand tile
#define LDSP 136
#define WTILE (128 * LDS32)
#define PTILE (32 * LDSP)

// ---------------- K1: score GEMM (R12 proven core) + optional symmetric mode ----------------
// sym=0: grid (64,64), tile (n0,m0) from (bx,by).
// sym=1: 1D grid of 2080 upper-triangle tiles (gen x gen); off-diagonal tiles also
//        mirror-write the transposed block, halving compute for the repulsion scores.
__global__ __launch_bounds__(128)
void score_wmma(int b_is_gen, int sym) {
    __shared__ __align__(32) __half sh[4 * TILE32];   // 40,960 B
    const int tid = threadIdx.x, lane = tid & 31, wid = tid >> 5;
    const int wm = (wid & 1) * 64, wn = (wid >> 1) * 64;

    int bx, by;
    if (sym) {
        int t = blockIdx.x;
        bx = (int)((-1.0 + sqrt(1.0 + 8.0 * (double)t)) * 0.5);
        while ((bx + 1) * (bx + 2) / 2 <= t) bx++;
        while (bx * (bx + 1) / 2 > t) bx--;
        by = t - bx * (bx + 1) / 2;      // by <= bx
    } else {
        bx = blockIdx.x; by = blockIdx.y;
    }
    const int m0 = by * 128, n0 = bx * 128;

    const __half* segA[3] = { g_genH, g_genH, g_genL };
    const __half* segB[3];
    if (b_is_gen) { segB[0] = g_genH; segB[1] = g_genL; segB[2] = g_genH; }
    else          { segB[0] = g_posH; segB[1] = g_posL; segB[2] = g_posH; }

    const int NTSEG = D_N / 32, NTT = 3 * NTSEG;

    auto issue = [&](int u, int s) {
        int seg = u / NTSEG, t = u - seg * NTSEG;
        const __half* A = segA[seg];
        const __half* B = segB[seg];
        __half* dA = sh + s * 2 * TILE32;
        __half* dB = dA + TILE32;
#pragma unroll
        for (int i = 0; i < 4; i++) {
            int f = i * 128 + tid, r = f >> 2, c = f & 3;
            __pipeline_memcpy_async(dA + r * LDS32 + c * 8,
                                    A + (size_t)(m0 + r) * D_N + t * 32 + c * 8, 16);
            __pipeline_memcpy_async(dB + r * LDS32 + c * 8,
                                    B + (size_t)(n0 + r) * D_N + t * 32 + c * 8, 16);
        }
        __pipeline_commit();
    };

    wmma::fragment<wmma::accumulator, 16, 16, 16, float> cfr[4][4];
#pragma unroll
    for (int i = 0; i < 4; i++)
#pragma unroll
        for (int j = 0; j < 4; j++) wmma::fill_fragment(cfr[i][j], 0.f);

    issue(0, 0);
    for (int u = 0; u < NTT; u++) {
        if (u + 1 < NTT) { issue(u + 1, (u + 1) & 1); __pipeline_wait_prior(1); }
        else             { __pipeline_wait_prior(0); }
        __syncthreads();
        const __half* bufA = sh + (u & 1) * 2 * TILE32;
        const __half* bufB = bufA + TILE32;
#pragma unroll
        for (int ks = 0; ks < 2; ks++) {
            wmma::fragment<wmma::matrix_a, 16, 16, 16, __half, wmma::row_major> afr[4];
            wmma::fragment<wmma::matrix_b, 16, 16, 16, __half, wmma::col_major> bfr[4];
#pragma unroll
            for (int i = 0; i < 4; i++)
                wmma::load_matrix_sync(afr[i], bufA + (wm + i * 16) * LDS32 + ks * 16, LDS32);
#pragma unroll
            for (int j = 0; j < 4; j++)
                wmma::load_matrix_sync(bfr[j], bufB + (wn + j * 16) * LDS32 + ks * 16, LDS32);
#pragma unroll
            for (int i = 0; i < 4; i++)
#pragma unroll
                for (int j = 0; j < 4; j++)
                    wmma::mma_sync(cfr[i][j], afr[i], bfr[j], cfr[i][j]);
        }
        __syncthreads();
    }

    // epilogue: per 16x16 patch -> transform -> write (+ mirror in symmetric off-diag tiles)
    float* patch = ((float*)sh) + wid * 256;
    const float* bnp = b_is_gen ? g_gn : g_pn;
    const int do_mirror = sym && (bx != by);
#pragma unroll
    for (int i = 0; i < 4; i++) {
#pragma unroll
        for (int j = 0; j < 4; j++) {
            wmma::store_matrix_sync(patch, cfr[i][j], 16, wmma::mem_row_major);
            __syncwarp();
            const int pr = lane >> 1, pc = (lane & 1) * 8;
            {   // normal block: S[m0+wm+i16+pr][n0+wn+j16+pc..+7]
                const int row = m0 + wm + i * 16 + pr;
                const int colb = n0 + wn + j * 16 + pc;
                const float an = g_gn[row];
                float4 bn0 = *(const float4*)(bnp + colb);
                float4 bn1 = *(const float4*)(bnp + colb + 4);
                const float* p = patch + pr * 16 + pc;
                float bns[8] = {bn0.x, bn0.y, bn0.z, bn0.w, bn1.x, bn1.y, bn1.z, bn1.w};
                float o[8];
#pragma unroll
                for (int e = 0; e < 8; e++) {
                    float d2 = fmaxf(an + bns[e] - 2.f * p[e], 0.f);
                    o[e] = -10.f * sqrtf(d2);
                }
                float* dst = g_S + (size_t)row * B_N + colb;
                *(float4*)dst       = make_float4(o[0], o[1], o[2], o[3]);
                *(float4*)(dst + 4) = make_float4(o[4], o[5], o[6], o[7]);
            }
            if (do_mirror) {
                // mirror block: S[n0+wn+j16+pr][m0+wm+i16+pc..+7] = S[col][row] (symmetric)
                const int mrow = n0 + wn + j * 16 + pr;        // gen index (was column)
                const int mcolb = m0 + wm + i * 16 + pc;       // gen index (was row)
                const float bnv = g_gn[mrow];
                float o[8];
#pragma unroll
                for (int e = 0; e < 8; e++) {
                    float an = g_gn[mcolb + e];
                    float d2 = fmaxf(an + bnv - 2.f * patch[(pc + e) * 16 + pr], 0.f);
                    o[e] = -10.f * sqrtf(d2);
                }
                float* dst = g_S + (size_t)mrow * B_N + mcolb;
                *(float4*)dst       = make_float4(o[0], o[1], o[2], o[3]);
                *(float4*)(dst + 4) = make_float4(o[4], o[5], o[6], o[7]);
            }
            __syncwarp();
        }
    }
}

// ---------------- K2: row softmax -> fp16 hi/lo weight planes in place (proven) ----------------
__global__ __launch_bounds__(256)
void softmax_w16(int mask_diag) {
    __shared__ float sm[B_N];
    int row = blockIdx.x;
    const float* Srow = g_S + (size_t)row * B_N;
    float mx = -INFINITY;
    for (int j = threadIdx.x; j < B_N; j += blockDim.x) {
        float v = Srow[j];
        if (mask_diag && j == row) v = -INFINITY;
        sm[j] = v;
        mx = fmaxf(mx, v);
    }
    mx = blockMax(mx);
    float sum = 0.f;
    for (int j = threadIdx.x; j < B_N; j += blockDim.x) {
        float e = expf(sm[j] - mx);
        sm[j] = e;
        sum += e;
    }
    sum = blockSum(sum);
    float inv = 1.f / sum;
    __syncthreads();
    __half* WH = (__half*)g_S + (size_t)row * (2 * B_N);
    __half* WL = WH + B_N;
    for (int j = threadIdx.x; j < B_N; j += blockDim.x) {
        float w = sm[j] * inv;
        __half h = __float2half(w);
        WH[j] = h;
        WL[j] = __float2half(w - __half2float(h));
    }
}

// ---------------- K3: wavg GEMM (R12 proven: flipped, static 2-stage) ----------------
__global__ __launch_bounds__(128)
void wavg_wmma(const float* __restrict__ sub, int to_rep) {
    __shared__ __align__(32) __half shW[2 * WTILE];
    __shared__ __align__(32) __half shP[2 * PTILE];
    const int tid = threadIdx.x, lane = tid & 31, wid = tid >> 5;
    const int w_nn = (wid & 1) * 64;
    const int w_m  = (wid >> 1) * 64;
    const int n0 = blockIdx.x * 128;
    const int m0 = blockIdx.y * 128;

    const __half* WHp = (const __half*)g_S;
    const __half* WLp = (const __half*)g_S + B_N;
    const __half* segW[3] = { WHp, WHp, WLp };
    const __half* segP[3];
    if (to_rep) { segP[0] = g_genH; segP[1] = g_genL; segP[2] = g_genH; }
    else        { segP[0] = g_posH; segP[1] = g_posL; segP[2] = g_posH; }

    const int NTSEG = B_N / 32, NTT = 3 * NTSEG;

    auto issue = [&](int u, int s) {
        int seg = u / NTSEG, t = u - seg * NTSEG;
        const __half* Wp = segW[seg];
        const __half* Pp = segP[seg];
        __half* dW = shW + s * WTILE;
        __half* dP = shP + s * PTILE;
#pragma unroll
        for (int i = 0; i < 4; i++) {
            int f = i * 128 + tid;
            int rw = f >> 2, cw = f & 3;
            __pipeline_memcpy_async(dW + rw * LDS32 + cw * 8,
                                    Wp + (size_t)(m0 + rw) * (2 * B_N) + t * 32 + cw * 8, 16);
            int rp = f >> 4, cp = f & 15;
            __pipeline_memcpy_async(dP + rp * LDSP + cp * 8,
                                    Pp + (size_t)(t * 32 + rp) * D_N + n0 + cp * 8, 16);
        }
        __pipeline_commit();
    };

    wmma::fragment<wmma::accumulator, 16, 16, 16, float> cfr[4][4];   // [nn][m]
#pragma unroll
    for (int i = 0; i < 4; i++)
#pragma unroll
        for (int j = 0; j < 4; j++) wmma::fill_fragment(cfr[i][j], 0.f);

    issue(0, 0);
    for (int u = 0; u < NTT; u++) {
        if (u + 1 < NTT) { issue(u + 1, (u + 1) & 1); __pipeline_wait_prior(1); }
        else             { __pipeline_wait_prior(0); }
        __syncthreads();
        const __half* bufW = shW + (u & 1) * WTILE;
        const __half* bufP = shP + (u & 1) * PTILE;
#pragma unroll
        for (int ks = 0; ks < 2; ks++) {
            wmma::fragment<wmma::matrix_a, 16, 16, 16, __half, wmma::col_major> afr[4];
            wmma::fragment<wmma::matrix_b, 16, 16, 16, __half, wmma::col_major> bfr[4];
#pragma unroll
            for (int i = 0; i < 4; i++)
                wmma::load_matrix_sync(afr[i], bufP + (ks * 16) * LDSP + w_nn + i * 16, LDSP);
#pragma unroll
            for (int j = 0; j < 4; j++)
                wmma::load_matrix_sync(bfr[j], bufW + (w_m + j * 16) * LDS32 + ks * 16, LDS32);
#pragma unroll
            for (int i = 0; i < 4; i++)
#pragma unroll
                for (int j = 0; j < 4; j++)
                    wmma::mma_sync(cfr[i][j], afr[i], bfr[j], cfr[i][j]);
        }
        __syncthreads();
    }

    float* outp = to_rep ? g_rep : g_attr;
    float* patch = ((float*)shW) + wid * 256;
#pragma unroll
    for (int i = 0; i < 4; i++) {
#pragma unroll
        for (int j = 0; j < 4; j++) {
            wmma::store_matrix_sync(patch, cfr[i][j], 16, wmma::mem_col_major);
            __syncwarp();
            const int pr = lane >> 1, pc = (lane & 1) * 8;
            const int m  = m0 + w_m + j * 16 + pr;
            const int nn = n0 + w_nn + i * 16 + pc;
            const float* p = patch + pr * 16 + pc;
            size_t base = (size_t)m * D_N + nn;
            float4 s0 = *(const float4*)(sub + base);
            float4 s1 = *(const float4*)(sub + base + 4);
            *(float4*)(outp + base)     = make_float4(p[0] - s0.x, p[1] - s0.y,
                                                      p[2] - s0.z, p[3] - s0.w);
            *(float4*)(outp + base + 4) = make_float4(p[4] - s1.x, p[5] - s1.y,
                                                      p[6] - s1.z, p[7] - s1.w);
            __syncwarp();
        }
    }
}

// ---------------- K4/K5: final reductions (proven) ----------------
__global__ __launch_bounds__(256)
void row_reduce() {
    int row = blockIdx.x;
    const float* a = g_attr + (size_t)row * D_N;
    const float* r = g_rep + (size_t)row * D_N;
    float sa = 0.f, sr = 0.f, sd = 0.f;
    for (int c = threadIdx.x * 4; c < D_N; c += blockDim.x * 4) {
        float4 av = *(const float4*)(a + c);
        float4 rv = *(const float4*)(r + c);
        float dx = av.x - rv.x, dy = av.y - rv.y, dz = av.z - rv.z, dw = av.w - rv.w;
        sa += av.x * av.x + av.y * av.y + av.z * av.z + av.w * av.w;
        sr += rv.x * rv.x + rv.y * rv.y + rv.z * rv.z + rv.w * rv.w;
        sd += dx * dx + dy * dy + dz * dz + dw * dw;
    }
    sa = blockSum(sa); sr = blockSum(sr); sd = blockSum(sd);
    if (threadIdx.x == 0) {
        g_part[row * 4 + 0] = sd;
        g_part[row * 4 + 1] = sqrtf(sd);
        g_part[row * 4 + 2] = sqrtf(sa);
        g_part[row * 4 + 3] = sqrtf(sr);
    }
}

__global__ __launch_bounds__(256)
void final_reduce(float* __restrict__ out) {
    float s0 = 0.f, s1 = 0.f, s2 = 0.f, s3 = 0.f;
    for (int i = threadIdx.x; i < B_N; i += blockDim.x) {
        s0 += g_part[i * 4 + 0]; s1 += g_part[i * 4 + 1];
        s2 += g_part[i * 4 + 2]; s3 += g_part[i * 4 + 3];
    }
    s0 = blockSum(s0); s1 = blockSum(s1); s2 = blockSum(s2); s3 = blockSum(s3);
    if (threadIdx.x == 0) {
        out[0] = s0 / ((float)B_N * (float)D_N);
        out[1] = s1 / (float)B_N;
        out[2] = s2 / (float)B_N;
        out[3] = s3 / (float)B_N;
    }
}

// ---------------- launch ----------------
extern "C" void kernel_launch(void* const* d_in, const int* in_sizes, int n_in,
                              void* d_out, int out_size) {
    const float* gen = (const float*)d_in[0];
    const float* pos = (const float*)d_in[1];
    float* out = (float*)d_out;

    prep_kernel<<<2 * B_N, 256>>>(gen, pos);

    // Attraction: scores(gen,pos) full grid -> softmax -> W@pos - gen
    score_wmma<<<dim3(64, 64), 128>>>(0, 0);
    softmax_w16<<<B_N, 256>>>(0);
    wavg_wmma<<<dim3(8, 64), 128>>>(gen, 0);

    // Repulsion: scores(gen,gen) SYMMETRIC (upper-triangle tiles only) -> softmax -> W@gen - gen
    score_wmma<<<dim3(64 * 65 / 2, 1), 128>>>(1, 1);
    softmax_w16<<<B_N, 256>>>(1);
    wavg_wmma<<<dim3(8, 64), 128>>>(gen, 1);

    row_reduce<<<B_N, 256>>>();
    final_reduce<<<1, 256>>>(out);
}

// round 15
// speedup vs baseline: 1.3680x; 1.2278x over previous
#include <cuda_runtime.h>
#include <cuda_fp16.h>
#include <cuda_pipeline.h>
#include <mma.h>
#include <math.h>
#include <stdint.h>

using namespace nvcuda;

// Problem constants (B=8192, B_pos=8192, D=1024, T=0.1)
#define B_N 8192
#define D_N 1024

// ---------------- scratch: EXACTLY the proven 384 MB set ----------------
// g_S doubles as fp32 score matrix, then per-row fp16 WH plane in place:
//   row r as halves: (half*)g_S + r*2*B_N ; [0..B_N)=WH  ([B_N..2*B_N) unused)
static __device__ __align__(256) float  g_S[(size_t)B_N * B_N];      // 256 MB
static __device__ __align__(256) __half g_genH[(size_t)B_N * D_N];   // 16 MB
static __device__ __align__(256) __half g_genL[(size_t)B_N * D_N];   // 16 MB
static __device__ __align__(256) __half g_posH[(size_t)B_N * D_N];   // 16 MB
static __device__ __align__(256) __half g_posL[(size_t)B_N * D_N];   // 16 MB
static __device__ __align__(256) float g_attr[(size_t)B_N * D_N];    // 32 MB
static __device__ __align__(256) float g_rep[(size_t)B_N * D_N];     // 32 MB
static __device__ float g_gn[B_N];
static __device__ float g_pn[B_N];
static __device__ float g_part[B_N * 4];

// ---------------- reductions (proven) ----------------
__device__ __forceinline__ float warpSum(float v) {
#pragma unroll
    for (int o = 16; o > 0; o >>= 1) v += __shfl_xor_sync(0xffffffffu, v, o);
    return v;
}
__device__ __forceinline__ float warpMax(float v) {
#pragma unroll
    for (int o = 16; o > 0; o >>= 1) v = fmaxf(v, __shfl_xor_sync(0xffffffffu, v, o));
    return v;
}
__device__ float blockSum(float v) {
    __shared__ float s[33];
    int lane = threadIdx.x & 31, w = threadIdx.x >> 5;
    __syncthreads();
    v = warpSum(v);
    if (lane == 0) s[w] = v;
    __syncthreads();
    if (w == 0) {
        float t = (threadIdx.x < (blockDim.x >> 5)) ? s[threadIdx.x] : 0.f;
        t = warpSum(t);
        if (lane == 0) s[32] = t;
    }
    __syncthreads();
    return s[32];
}
__device__ float blockMax(float v) {
    __shared__ float s[33];
    int lane = threadIdx.x & 31, w = threadIdx.x >> 5;
    __syncthreads();
    v = warpMax(v);
    if (lane == 0) s[w] = v;
    __syncthreads();
    if (w == 0) {
        float t = (threadIdx.x < (blockDim.x >> 5)) ? s[threadIdx.x] : -INFINITY;
        t = warpMax(t);
        if (lane == 0) s[32] = t;
    }
    __syncthreads();
    return s[32];
}

// ---------------- K0: fused row norms + fp16 hi/lo plane split (proven) ----------------
__global__ __launch_bounds__(256)
void prep_kernel(const float* __restrict__ gen, const float* __restrict__ pos) {
    int row = blockIdx.x;
    const float* src; __half *H, *L; float* dst;
    if (row < B_N) {
        src = gen + (size_t)row * D_N;
        H = g_genH + (size_t)row * D_N; L = g_genL + (size_t)row * D_N;
        dst = &g_gn[row];
    } else {
        int r = row - B_N;
        src = pos + (size_t)r * D_N;
        H = g_posH + (size_t)r * D_N; L = g_posL + (size_t)r * D_N;
        dst = &g_pn[r];
    }
    float s = 0.f;
    for (int c = threadIdx.x * 4; c < D_N; c += blockDim.x * 4) {
        float4 v = *(const float4*)(src + c);
        s += v.x * v.x + v.y * v.y + v.z * v.z + v.w * v.w;
        __half hx = __float2half(v.x), hy = __float2half(v.y);
        __half hz = __float2half(v.z), hw = __float2half(v.w);
        *(__half2*)(H + c)     = __halves2half2(hx, hy);
        *(__half2*)(H + c + 2) = __halves2half2(hz, hw);
        *(__half2*)(L + c)     = __halves2half2(__float2half(v.x - __half2float(hx)),
                                                __float2half(v.y - __half2float(hy)));
        *(__half2*)(L + c + 2) = __halves2half2(__float2half(v.z - __half2float(hz)),
                                                __float2half(v.w - __half2float(hw)));
    }
    s = blockSum(s);
    if (threadIdx.x == 0) *dst = s;
}

#define LDS32 40                   // padded smem stride in halves (32 + 8)
#define TILE32 (128 * LDS32)       // 5120 halves per operand tile
#define LDSP 136
#define WTILE (128 * LDS32)
#define PTILE (32 * LDSP)

// ---------------- K1: score GEMM (proven) + symmetric mode for gen x gen ----------------
__global__ __launch_bounds__(128)
void score_wmma(int b_is_gen, int sym) {
    __shared__ __align__(32) __half sh[4 * TILE32];   // 40,960 B
    const int tid = threadIdx.x, lane = tid & 31, wid = tid >> 5;
    const int wm = (wid & 1) * 64, wn = (wid >> 1) * 64;

    int bx, by;
    if (sym) {
        int t = blockIdx.x;
        bx = (int)((-1.0 + sqrt(1.0 + 8.0 * (double)t)) * 0.5);
        while ((bx + 1) * (bx + 2) / 2 <= t) bx++;
        while (bx * (bx + 1) / 2 > t) bx--;
        by = t - bx * (bx + 1) / 2;      // by <= bx
    } else {
        bx = blockIdx.x; by = blockIdx.y;
    }
    const int m0 = by * 128, n0 = bx * 128;

    const __half* segA[3] = { g_genH, g_genH, g_genL };
    const __half* segB[3];
    if (b_is_gen) { segB[0] = g_genH; segB[1] = g_genL; segB[2] = g_genH; }
    else          { segB[0] = g_posH; segB[1] = g_posL; segB[2] = g_posH; }

    const int NTSEG = D_N / 32, NTT = 3 * NTSEG;

    auto issue = [&](int u, int s) {
        int seg = u / NTSEG, t = u - seg * NTSEG;
        const __half* A = segA[seg];
        const __half* B = segB[seg];
        __half* dA = sh + s * 2 * TILE32;
        __half* dB = dA + TILE32;
#pragma unroll
        for (int i = 0; i < 4; i++) {
            int f = i * 128 + tid, r = f >> 2, c = f & 3;
            __pipeline_memcpy_async(dA + r * LDS32 + c * 8,
                                    A + (size_t)(m0 + r) * D_N + t * 32 + c * 8, 16);
            __pipeline_memcpy_async(dB + r * LDS32 + c * 8,
                                    B + (size_t)(n0 + r) * D_N + t * 32 + c * 8, 16);
        }
        __pipeline_commit();
    };

    wmma::fragment<wmma::accumulator, 16, 16, 16, float> cfr[4][4];
#pragma unroll
    for (int i = 0; i < 4; i++)
#pragma unroll
        for (int j = 0; j < 4; j++) wmma::fill_fragment(cfr[i][j], 0.f);

    issue(0, 0);
    for (int u = 0; u < NTT; u++) {
        if (u + 1 < NTT) { issue(u + 1, (u + 1) & 1); __pipeline_wait_prior(1); }
        else             { __pipeline_wait_prior(0); }
        __syncthreads();
        const __half* bufA = sh + (u & 1) * 2 * TILE32;
        const __half* bufB = bufA + TILE32;
#pragma unroll
        for (int ks = 0; ks < 2; ks++) {
            wmma::fragment<wmma::matrix_a, 16, 16, 16, __half, wmma::row_major> afr[4];
            wmma::fragment<wmma::matrix_b, 16, 16, 16, __half, wmma::col_major> bfr[4];
#pragma unroll
            for (int i = 0; i < 4; i++)
                wmma::load_matrix_sync(afr[i], bufA + (wm + i * 16) * LDS32 + ks * 16, LDS32);
#pragma unroll
            for (int j = 0; j < 4; j++)
                wmma::load_matrix_sync(bfr[j], bufB + (wn + j * 16) * LDS32 + ks * 16, LDS32);
#pragma unroll
            for (int i = 0; i < 4; i++)
#pragma unroll
                for (int j = 0; j < 4; j++)
                    wmma::mma_sync(cfr[i][j], afr[i], bfr[j], cfr[i][j]);
        }
        __syncthreads();
    }

    // epilogue: per 16x16 patch -> transform -> write (+ mirror in symmetric off-diag tiles)
    float* patch = ((float*)sh) + wid * 256;
    const float* bnp = b_is_gen ? g_gn : g_pn;
    const int do_mirror = sym && (bx != by);
#pragma unroll
    for (int i = 0; i < 4; i++) {
#pragma unroll
        for (int j = 0; j < 4; j++) {
            wmma::store_matrix_sync(patch, cfr[i][j], 16, wmma::mem_row_major);
            __syncwarp();
            const int pr = lane >> 1, pc = (lane & 1) * 8;
            {
                const int row = m0 + wm + i * 16 + pr;
                const int colb = n0 + wn + j * 16 + pc;
                const float an = g_gn[row];
                float4 bn0 = *(const float4*)(bnp + colb);
                float4 bn1 = *(const float4*)(bnp + colb + 4);
                const float* p = patch + pr * 16 + pc;
                float bns[8] = {bn0.x, bn0.y, bn0.z, bn0.w, bn1.x, bn1.y, bn1.z, bn1.w};
                float o[8];
#pragma unroll
                for (int e = 0; e < 8; e++) {
                    float d2 = fmaxf(an + bns[e] - 2.f * p[e], 0.f);
                    o[e] = -10.f * sqrtf(d2);
                }
                float* dst = g_S + (size_t)row * B_N + colb;
                *(float4*)dst       = make_float4(o[0], o[1], o[2], o[3]);
                *(float4*)(dst + 4) = make_float4(o[4], o[5], o[6], o[7]);
            }
            if (do_mirror) {
                const int mrow = n0 + wn + j * 16 + pr;
                const int mcolb = m0 + wm + i * 16 + pc;
                const float bnv = g_gn[mrow];
                float o[8];
#pragma unroll
                for (int e = 0; e < 8; e++) {
                    float an = g_gn[mcolb + e];
                    float d2 = fmaxf(an + bnv - 2.f * patch[(pc + e) * 16 + pr], 0.f);
                    o[e] = -10.f * sqrtf(d2);
                }
                float* dst = g_S + (size_t)mrow * B_N + mcolb;
                *(float4*)dst       = make_float4(o[0], o[1], o[2], o[3]);
                *(float4*)(dst + 4) = make_float4(o[4], o[5], o[6], o[7]);
            }
            __syncwarp();
        }
    }
}

// ---------------- K2: row softmax -> fp16 WH plane in place (WL dropped: unused by wavg) ----
__global__ __launch_bounds__(256)
void softmax_w16(int mask_diag) {
    __shared__ float sm[B_N];
    int row = blockIdx.x;
    const float* Srow = g_S + (size_t)row * B_N;
    float mx = -INFINITY;
    for (int j = threadIdx.x; j < B_N; j += blockDim.x) {
        float v = Srow[j];
        if (mask_diag && j == row) v = -INFINITY;
        sm[j] = v;
        mx = fmaxf(mx, v);
    }
    mx = blockMax(mx);
    float sum = 0.f;
    for (int j = threadIdx.x; j < B_N; j += blockDim.x) {
        float e = expf(sm[j] - mx);
        sm[j] = e;
        sum += e;
    }
    sum = blockSum(sum);
    float inv = 1.f / sum;
    __syncthreads();
    __half* WH = (__half*)g_S + (size_t)row * (2 * B_N);
    for (int j = threadIdx.x; j < B_N; j += blockDim.x)
        WH[j] = __float2half(sm[j] * inv);
}

// ---------------- K3: wavg GEMM (flipped, proven) -- TWO segments: WH·PH + WH·PL = WH·P ----
// Dropped WL·PH term: |WL| <= 2^-12 * w, error random-signed -> ~1e-5 on aggregated outputs.
__global__ __launch_bounds__(128)
void wavg_wmma(const float* __restrict__ sub, int to_rep) {
    __shared__ __align__(32) __half shW[2 * WTILE];
    __shared__ __align__(32) __half shP[2 * PTILE];
    const int tid = threadIdx.x, lane = tid & 31, wid = tid >> 5;
    const int w_nn = (wid & 1) * 64;
    const int w_m  = (wid >> 1) * 64;
    const int n0 = blockIdx.x * 128;
    const int m0 = blockIdx.y * 128;

    const __half* WHp = (const __half*)g_S;
    const __half* segW[2] = { WHp, WHp };
    const __half* segP[2];
    if (to_rep) { segP[0] = g_genH; segP[1] = g_genL; }
    else        { segP[0] = g_posH; segP[1] = g_posL; }

    const int NTSEG = B_N / 32, NTT = 2 * NTSEG;     // 512 k-tiles total (was 768)

    auto issue = [&](int u, int s) {
        int seg = u / NTSEG, t = u - seg * NTSEG;
        const __half* Wp = segW[seg];
        const __half* Pp = segP[seg];
        __half* dW = shW + s * WTILE;
        __half* dP = shP + s * PTILE;
#pragma unroll
        for (int i = 0; i < 4; i++) {
            int f = i * 128 + tid;
            int rw = f >> 2, cw = f & 3;
            __pipeline_memcpy_async(dW + rw * LDS32 + cw * 8,
                                    Wp + (size_t)(m0 + rw) * (2 * B_N) + t * 32 + cw * 8, 16);
            int rp = f >> 4, cp = f & 15;
            __pipeline_memcpy_async(dP + rp * LDSP + cp * 8,
                                    Pp + (size_t)(t * 32 + rp) * D_N + n0 + cp * 8, 16);
        }
        __pipeline_commit();
    };

    wmma::fragment<wmma::accumulator, 16, 16, 16, float> cfr[4][4];   // [nn][m]
#pragma unroll
    for (int i = 0; i < 4; i++)
#pragma unroll
        for (int j = 0; j < 4; j++) wmma::fill_fragment(cfr[i][j], 0.f);

    issue(0, 0);
    for (int u = 0; u < NTT; u++) {
        if (u + 1 < NTT) { issue(u + 1, (u + 1) & 1); __pipeline_wait_prior(1); }
        else             { __pipeline_wait_prior(0); }
        __syncthreads();
        const __half* bufW = shW + (u & 1) * WTILE;
        const __half* bufP = shP + (u & 1) * PTILE;
#pragma unroll
        for (int ks = 0; ks < 2; ks++) {
            wmma::fragment<wmma::matrix_a, 16, 16, 16, __half, wmma::col_major> afr[4];
            wmma::fragment<wmma::matrix_b, 16, 16, 16, __half, wmma::col_major> bfr[4];
#pragma unroll
            for (int i = 0; i < 4; i++)
                wmma::load_matrix_sync(afr[i], bufP + (ks * 16) * LDSP + w_nn + i * 16, LDSP);
#pragma unroll
            for (int j = 0; j < 4; j++)
                wmma::load_matrix_sync(bfr[j], bufW + (w_m + j * 16) * LDS32 + ks * 16, LDS32);
#pragma unroll
            for (int i = 0; i < 4; i++)
#pragma unroll
                for (int j = 0; j < 4; j++)
                    wmma::mma_sync(cfr[i][j], afr[i], bfr[j], cfr[i][j]);
        }
        __syncthreads();
    }

    float* outp = to_rep ? g_rep : g_attr;
    float* patch = ((float*)shW) + wid * 256;
#pragma unroll
    for (int i = 0; i < 4; i++) {
#pragma unroll
        for (int j = 0; j < 4; j++) {
            wmma::store_matrix_sync(patch, cfr[i][j], 16, wmma::mem_col_major);
            __syncwarp();
            const int pr = lane >> 1, pc = (lane & 1) * 8;
            const int m  = m0 + w_m + j * 16 + pr;
            const int nn = n0 + w_nn + i * 16 + pc;
            const float* p = patch + pr * 16 + pc;
            size_t base = (size_t)m * D_N + nn;
            float4 s0 = *(const float4*)(sub + base);
            float4 s1 = *(const float4*)(sub + base + 4);
            *(float4*)(outp + base)     = make_float4(p[0] - s0.x, p[1] - s0.y,
                                                      p[2] - s0.z, p[3] - s0.w);
            *(float4*)(outp + base + 4) = make_float4(p[4] - s1.x, p[5] - s1.y,
                                                      p[6] - s1.z, p[7] - s1.w);
            __syncwarp();
        }
    }
}

// ---------------- K4/K5: final reductions (proven) ----------------
__global__ __launch_bounds__(256)
void row_reduce() {
    int row = blockIdx.x;
    const float* a = g_attr + (size_t)row * D_N;
    const float* r = g_rep + (size_t)row * D_N;
    float sa = 0.f, sr = 0.f, sd = 0.f;
    for (int c = threadIdx.x * 4; c < D_N; c += blockDim.x * 4) {
        float4 av = *(const float4*)(a + c);
        float4 rv = *(const float4*)(r + c);
        float dx = av.x - rv.x, dy = av.y - rv.y, dz = av.z - rv.z, dw = av.w - rv.w;
        sa += av.x * av.x + av.y * av.y + av.z * av.z + av.w * av.w;
        sr += rv.x * rv.x + rv.y * rv.y + rv.z * rv.z + rv.w * rv.w;
        sd += dx * dx + dy * dy + dz * dz + dw * dw;
    }
    sa = blockSum(sa); sr = blockSum(sr); sd = blockSum(sd);
    if (threadIdx.x == 0) {
        g_part[row * 4 + 0] = sd;
        g_part[row * 4 + 1] = sqrtf(sd);
        g_part[row * 4 + 2] = sqrtf(sa);
        g_part[row * 4 + 3] = sqrtf(sr);
    }
}

__global__ __launch_bounds__(256)
void final_reduce(float* __restrict__ out) {
    float s0 = 0.f, s1 = 0.f, s2 = 0.f, s3 = 0.f;
    for (int i = threadIdx.x; i < B_N; i += blockDim.x) {
        s0 += g_part[i * 4 + 0]; s1 += g_part[i * 4 + 1];
        s2 += g_part[i * 4 + 2]; s3 += g_part[i * 4 + 3];
    }
    s0 = blockSum(s0); s1 = blockSum(s1); s2 = blockSum(s2); s3 = blockSum(s3);
    if (threadIdx.x == 0) {
        out[0] = s0 / ((float)B_N * (float)D_N);
        out[1] = s1 / (float)B_N;
        out[2] = s2 / (float)B_N;
        out[3] = s3 / (float)B_N;
    }
}

// ---------------- launch ----------------
extern "C" void kernel_launch(void* const* d_in, const int* in_sizes, int n_in,
                              void* d_out, int out_size) {
    const float* gen = (const float*)d_in[0];
    const float* pos = (const float*)d_in[1];
    float* out = (float*)d_out;

    prep_kernel<<<2 * B_N, 256>>>(gen, pos);

    // Attraction: scores(gen,pos) full grid -> softmax -> W@pos - gen
    score_wmma<<<dim3(64, 64), 128>>>(0, 0);
    softmax_w16<<<B_N, 256>>>(0);
    wavg_wmma<<<dim3(8, 64), 128>>>(gen, 0);

    // Repulsion: scores(gen,gen) SYMMETRIC (upper-triangle tiles) -> softmax -> W@gen - gen
    score_wmma<<<dim3(64 * 65 / 2, 1), 128>>>(1, 1);
    softmax_w16<<<B_N, 256>>>(1);
    wavg_wmma<<<dim3(8, 64), 128>>>(gen, 1);

    row_reduce<<<B_N, 256>>>();
    final_reduce<<<1, 256>>>(out);
}

// round 16
// speedup vs baseline: 1.6048x; 1.1731x over previous
#include <cuda_runtime.h>
#include <cuda_fp16.h>
#include <cuda_pipeline.h>
#include <mma.h>
#include <math.h>
#include <stdint.h>

using namespace nvcuda;

// Problem constants (B=8192, B_pos=8192, D=1024, T=0.1)
#define B_N 8192
#define D_N 1024

// ---------------- scratch: EXACTLY the proven 384 MB set ----------------
// g_S doubles as fp32 score matrix, then per-row fp16 WH plane in place:
//   row r as halves: (half*)g_S + r*2*B_N ; [0..B_N)=WH
static __device__ __align__(256) float  g_S[(size_t)B_N * B_N];      // 256 MB
static __device__ __align__(256) __half g_genH[(size_t)B_N * D_N];   // 16 MB
static __device__ __align__(256) __half g_genL[(size_t)B_N * D_N];   // 16 MB
static __device__ __align__(256) __half g_posH[(size_t)B_N * D_N];   // 16 MB
static __device__ __align__(256) __half g_posL[(size_t)B_N * D_N];   // 16 MB
static __device__ __align__(256) float g_attr[(size_t)B_N * D_N];    // 32 MB
static __device__ __align__(256) float g_rep[(size_t)B_N * D_N];     // 32 MB
static __device__ float g_gn[B_N];
static __device__ float g_pn[B_N];
static __device__ float g_part[B_N * 4];

// ---------------- reductions (proven) ----------------
__device__ __forceinline__ float warpSum(float v) {
#pragma unroll
    for (int o = 16; o > 0; o >>= 1) v += __shfl_xor_sync(0xffffffffu, v, o);
    return v;
}
__device__ __forceinline__ float warpMax(float v) {
#pragma unroll
    for (int o = 16; o > 0; o >>= 1) v = fmaxf(v, __shfl_xor_sync(0xffffffffu, v, o));
    return v;
}
__device__ float blockSum(float v) {
    __shared__ float s[33];
    int lane = threadIdx.x & 31, w = threadIdx.x >> 5;
    __syncthreads();
    v = warpSum(v);
    if (lane == 0) s[w] = v;
    __syncthreads();
    if (w == 0) {
        float t = (threadIdx.x < (blockDim.x >> 5)) ? s[threadIdx.x] : 0.f;
        t = warpSum(t);
        if (lane == 0) s[32] = t;
    }
    __syncthreads();
    return s[32];
}
__device__ float blockMax(float v) {
    __shared__ float s[33];
    int lane = threadIdx.x & 31, w = threadIdx.x >> 5;
    __syncthreads();
    v = warpMax(v);
    if (lane == 0) s[w] = v;
    __syncthreads();
    if (w == 0) {
        float t = (threadIdx.x < (blockDim.x >> 5)) ? s[threadIdx.x] : -INFINITY;
        t = warpMax(t);
        if (lane == 0) s[32] = t;
    }
    __syncthreads();
    return s[32];
}

// ---------------- K0: fused row norms + fp16 hi/lo plane split (proven) ----------------
__global__ __launch_bounds__(256)
void prep_kernel(const float* __restrict__ gen, const float* __restrict__ pos) {
    int row = blockIdx.x;
    const float* src; __half *H, *L; float* dst;
    if (row < B_N) {
        src = gen + (size_t)row * D_N;
        H = g_genH + (size_t)row * D_N; L = g_genL + (size_t)row * D_N;
        dst = &g_gn[row];
    } else {
        int r = row - B_N;
        src = pos + (size_t)r * D_N;
        H = g_posH + (size_t)r * D_N; L = g_posL + (size_t)r * D_N;
        dst = &g_pn[r];
    }
    float s = 0.f;
    for (int c = threadIdx.x * 4; c < D_N; c += blockDim.x * 4) {
        float4 v = *(const float4*)(src + c);
        s += v.x * v.x + v.y * v.y + v.z * v.z + v.w * v.w;
        __half hx = __float2half(v.x), hy = __float2half(v.y);
        __half hz = __float2half(v.z), hw = __float2half(v.w);
        *(__half2*)(H + c)     = __halves2half2(hx, hy);
        *(__half2*)(H + c + 2) = __halves2half2(hz, hw);
        *(__half2*)(L + c)     = __halves2half2(__float2half(v.x - __half2float(hx)),
                                                __float2half(v.y - __half2float(hy)));
        *(__half2*)(L + c + 2) = __halves2half2(__float2half(v.z - __half2float(hz)),
                                                __float2half(v.w - __half2float(hw)));
    }
    s = blockSum(s);
    if (threadIdx.x == 0) *dst = s;
}

#define LDS32 40                   // padded smem stride in halves (32 + 8)
#define TILE32 (128 * LDS32)       // 5120 halves per operand tile
#define LDSP 136
#define WTILE (128 * LDS32)
#define PTILE (32 * LDSP)

// ---------------- K1: score GEMM -- TWO segments: gH·pH + gH·pL = gH·p ----------------
// (Dropped gL·pH: logit error ~1.7e-3 absolute, zero-mean random across pairs.)
// sym=1: 1D grid of 2080 upper-triangle gen x gen tiles + mirror writes.
__global__ __launch_bounds__(128)
void score_wmma(int b_is_gen, int sym) {
    __shared__ __align__(32) __half sh[4 * TILE32];   // 40,960 B
    const int tid = threadIdx.x, lane = tid & 31, wid = tid >> 5;
    const int wm = (wid & 1) * 64, wn = (wid >> 1) * 64;

    int bx, by;
    if (sym) {
        int t = blockIdx.x;
        bx = (int)((-1.0 + sqrt(1.0 + 8.0 * (double)t)) * 0.5);
        while ((bx + 1) * (bx + 2) / 2 <= t) bx++;
        while (bx * (bx + 1) / 2 > t) bx--;
        by = t - bx * (bx + 1) / 2;      // by <= bx
    } else {
        bx = blockIdx.x; by = blockIdx.y;
    }
    const int m0 = by * 128, n0 = bx * 128;

    const __half* segA[2] = { g_genH, g_genH };
    const __half* segB[2];
    if (b_is_gen) { segB[0] = g_genH; segB[1] = g_genL; }
    else          { segB[0] = g_posH; segB[1] = g_posL; }

    const int NTSEG = D_N / 32, NTT = 2 * NTSEG;     // 64 k-tiles (was 96)

    auto issue = [&](int u, int s) {
        int seg = u / NTSEG, t = u - seg * NTSEG;
        const __half* A = segA[seg];
        const __half* B = segB[seg];
        __half* dA = sh + s * 2 * TILE32;
        __half* dB = dA + TILE32;
#pragma unroll
        for (int i = 0; i < 4; i++) {
            int f = i * 128 + tid, r = f >> 2, c = f & 3;
            __pipeline_memcpy_async(dA + r * LDS32 + c * 8,
                                    A + (size_t)(m0 + r) * D_N + t * 32 + c * 8, 16);
            __pipeline_memcpy_async(dB + r * LDS32 + c * 8,
                                    B + (size_t)(n0 + r) * D_N + t * 32 + c * 8, 16);
        }
        __pipeline_commit();
    };

    wmma::fragment<wmma::accumulator, 16, 16, 16, float> cfr[4][4];
#pragma unroll
    for (int i = 0; i < 4; i++)
#pragma unroll
        for (int j = 0; j < 4; j++) wmma::fill_fragment(cfr[i][j], 0.f);

    issue(0, 0);
    for (int u = 0; u < NTT; u++) {
        if (u + 1 < NTT) { issue(u + 1, (u + 1) & 1); __pipeline_wait_prior(1); }
        else             { __pipeline_wait_prior(0); }
        __syncthreads();
        const __half* bufA = sh + (u & 1) * 2 * TILE32;
        const __half* bufB = bufA + TILE32;
#pragma unroll
        for (int ks = 0; ks < 2; ks++) {
            wmma::fragment<wmma::matrix_a, 16, 16, 16, __half, wmma::row_major> afr[4];
            wmma::fragment<wmma::matrix_b, 16, 16, 16, __half, wmma::col_major> bfr[4];
#pragma unroll
            for (int i = 0; i < 4; i++)
                wmma::load_matrix_sync(afr[i], bufA + (wm + i * 16) * LDS32 + ks * 16, LDS32);
#pragma unroll
            for (int j = 0; j < 4; j++)
                wmma::load_matrix_sync(bfr[j], bufB + (wn + j * 16) * LDS32 + ks * 16, LDS32);
#pragma unroll
            for (int i = 0; i < 4; i++)
#pragma unroll
                for (int j = 0; j < 4; j++)
                    wmma::mma_sync(cfr[i][j], afr[i], bfr[j], cfr[i][j]);
        }
        __syncthreads();
    }

    // epilogue: per 16x16 patch -> transform -> write (+ mirror in symmetric off-diag tiles)
    float* patch = ((float*)sh) + wid * 256;
    const float* bnp = b_is_gen ? g_gn : g_pn;
    const int do_mirror = sym && (bx != by);
#pragma unroll
    for (int i = 0; i < 4; i++) {
#pragma unroll
        for (int j = 0; j < 4; j++) {
            wmma::store_matrix_sync(patch, cfr[i][j], 16, wmma::mem_row_major);
            __syncwarp();
            const int pr = lane >> 1, pc = (lane & 1) * 8;
            {
                const int row = m0 + wm + i * 16 + pr;
                const int colb = n0 + wn + j * 16 + pc;
                const float an = g_gn[row];
                float4 bn0 = *(const float4*)(bnp + colb);
                float4 bn1 = *(const float4*)(bnp + colb + 4);
                const float* p = patch + pr * 16 + pc;
                float bns[8] = {bn0.x, bn0.y, bn0.z, bn0.w, bn1.x, bn1.y, bn1.z, bn1.w};
                float o[8];
#pragma unroll
                for (int e = 0; e < 8; e++) {
                    float d2 = fmaxf(an + bns[e] - 2.f * p[e], 0.f);
                    o[e] = -10.f * sqrtf(d2);
                }
                float* dst = g_S + (size_t)row * B_N + colb;
                *(float4*)dst       = make_float4(o[0], o[1], o[2], o[3]);
                *(float4*)(dst + 4) = make_float4(o[4], o[5], o[6], o[7]);
            }
            if (do_mirror) {
                const int mrow = n0 + wn + j * 16 + pr;
                const int mcolb = m0 + wm + i * 16 + pc;
                const float bnv = g_gn[mrow];
                float o[8];
#pragma unroll
                for (int e = 0; e < 8; e++) {
                    float an = g_gn[mcolb + e];
                    float d2 = fmaxf(an + bnv - 2.f * patch[(pc + e) * 16 + pr], 0.f);
                    o[e] = -10.f * sqrtf(d2);
                }
                float* dst = g_S + (size_t)mrow * B_N + mcolb;
                *(float4*)dst       = make_float4(o[0], o[1], o[2], o[3]);
                *(float4*)(dst + 4) = make_float4(o[4], o[5], o[6], o[7]);
            }
            __syncwarp();
        }
    }
}

// ---------------- K2: row softmax -> fp16 WH plane in place (proven) ----------------
__global__ __launch_bounds__(256)
void softmax_w16(int mask_diag) {
    __shared__ float sm[B_N];
    int row = blockIdx.x;
    const float* Srow = g_S + (size_t)row * B_N;
    float mx = -INFINITY;
    for (int j = threadIdx.x; j < B_N; j += blockDim.x) {
        float v = Srow[j];
        if (mask_diag && j == row) v = -INFINITY;
        sm[j] = v;
        mx = fmaxf(mx, v);
    }
    mx = blockMax(mx);
    float sum = 0.f;
    for (int j = threadIdx.x; j < B_N; j += blockDim.x) {
        float e = expf(sm[j] - mx);
        sm[j] = e;
        sum += e;
    }
    sum = blockSum(sum);
    float inv = 1.f / sum;
    __syncthreads();
    __half* WH = (__half*)g_S + (size_t)row * (2 * B_N);
    for (int j = threadIdx.x; j < B_N; j += blockDim.x)
        WH[j] = __float2half(sm[j] * inv);
}

// ---------------- K3: wavg GEMM (proven R15: flipped, 2 segments WH·PH + WH·PL) ----------------
__global__ __launch_bounds__(128)
void wavg_wmma(const float* __restrict__ sub, int to_rep) {
    __shared__ __align__(32) __half shW[2 * WTILE];
    __shared__ __align__(32) __half shP[2 * PTILE];
    const int tid = threadIdx.x, lane = tid & 31, wid = tid >> 5;
    const int w_nn = (wid & 1) * 64;
    const int w_m  = (wid >> 1) * 64;
    const int n0 = blockIdx.x * 128;
    const int m0 = blockIdx.y * 128;

    const __half* WHp = (const __half*)g_S;
    const __half* segW[2] = { WHp, WHp };
    const __half* segP[2];
    if (to_rep) { segP[0] = g_genH; segP[1] = g_genL; }
    else        { segP[0] = g_posH; segP[1] = g_posL; }

    const int NTSEG = B_N / 32, NTT = 2 * NTSEG;

    auto issue = [&](int u, int s) {
        int seg = u / NTSEG, t = u - seg * NTSEG;
        const __half* Wp = segW[seg];
        const __half* Pp = segP[seg];
        __half* dW = shW + s * WTILE;
        __half* dP = shP + s * PTILE;
#pragma unroll
        for (int i = 0; i < 4; i++) {
            int f = i * 128 + tid;
            int rw = f >> 2, cw = f & 3;
            __pipeline_memcpy_async(dW + rw * LDS32 + cw * 8,
                                    Wp + (size_t)(m0 + rw) * (2 * B_N) + t * 32 + cw * 8, 16);
            int rp = f >> 4, cp = f & 15;
            __pipeline_memcpy_async(dP + rp * LDSP + cp * 8,
                                    Pp + (size_t)(t * 32 + rp) * D_N + n0 + cp * 8, 16);
        }
        __pipeline_commit();
    };

    wmma::fragment<wmma::accumulator, 16, 16, 16, float> cfr[4][4];   // [nn][m]
#pragma unroll
    for (int i = 0; i < 4; i++)
#pragma unroll
        for (int j = 0; j < 4; j++) wmma::fill_fragment(cfr[i][j], 0.f);

    issue(0, 0);
    for (int u = 0; u < NTT; u++) {
        if (u + 1 < NTT) { issue(u + 1, (u + 1) & 1); __pipeline_wait_prior(1); }
        else             { __pipeline_wait_prior(0); }
        __syncthreads();
        const __half* bufW = shW + (u & 1) * WTILE;
        const __half* bufP = shP + (u & 1) * PTILE;
#pragma unroll
        for (int ks = 0; ks < 2; ks++) {
            wmma::fragment<wmma::matrix_a, 16, 16, 16, __half, wmma::col_major> afr[4];
            wmma::fragment<wmma::matrix_b, 16, 16, 16, __half, wmma::col_major> bfr[4];
#pragma unroll
            for (int i = 0; i < 4; i++)
                wmma::load_matrix_sync(afr[i], bufP + (ks * 16) * LDSP + w_nn + i * 16, LDSP);
#pragma unroll
            for (int j = 0; j < 4; j++)
                wmma::load_matrix_sync(bfr[j], bufW + (w_m + j * 16) * LDS32 + ks * 16, LDS32);
#pragma unroll
            for (int i = 0; i < 4; i++)
#pragma unroll
                for (int j = 0; j < 4; j++)
                    wmma::mma_sync(cfr[i][j], afr[i], bfr[j], cfr[i][j]);
        }
        __syncthreads();
    }

    float* outp = to_rep ? g_rep : g_attr;
    float* patch = ((float*)shW) + wid * 256;
#pragma unroll
    for (int i = 0; i < 4; i++) {
#pragma unroll
        for (int j = 0; j < 4; j++) {
            wmma::store_matrix_sync(patch, cfr[i][j], 16, wmma::mem_col_major);
            __syncwarp();
            const int pr = lane >> 1, pc = (lane & 1) * 8;
            const int m  = m0 + w_m + j * 16 + pr;
            const int nn = n0 + w_nn + i * 16 + pc;
            const float* p = patch + pr * 16 + pc;
            size_t base = (size_t)m * D_N + nn;
            float4 s0 = *(const float4*)(sub + base);
            float4 s1 = *(const float4*)(sub + base + 4);
            *(float4*)(outp + base)     = make_float4(p[0] - s0.x, p[1] - s0.y,
                                                      p[2] - s0.z, p[3] - s0.w);
            *(float4*)(outp + base + 4) = make_float4(p[4] - s1.x, p[5] - s1.y,
                                                      p[6] - s1.z, p[7] - s1.w);
            __syncwarp();
        }
    }
}

// ---------------- K4/K5: final reductions (proven) ----------------
__global__ __launch_bounds__(256)
void row_reduce() {
    int row = blockIdx.x;
    const float* a = g_attr + (size_t)row * D_N;
    const float* r = g_rep + (size_t)row * D_N;
    float sa = 0.f, sr = 0.f, sd = 0.f;
    for (int c = threadIdx.x * 4; c < D_N; c += blockDim.x * 4) {
        float4 av = *(const float4*)(a + c);
        float4 rv = *(const float4*)(r + c);
        float dx = av.x - rv.x, dy = av.y - rv.y, dz = av.z - rv.z, dw = av.w - rv.w;
        sa += av.x * av.x + av.y * av.y + av.z * av.z + av.w * av.w;
        sr += rv.x * rv.x + rv.y * rv.y + rv.z * rv.z + rv.w * rv.w;
        sd += dx * dx + dy * dy + dz * dz + dw * dw;
    }
    sa = blockSum(sa); sr = blockSum(sr); sd = blockSum(sd);
    if (threadIdx.x == 0) {
        g_part[row * 4 + 0] = sd;
        g_part[row * 4 + 1] = sqrtf(sd);
        g_part[row * 4 + 2] = sqrtf(sa);
        g_part[row * 4 + 3] = sqrtf(sr);
    }
}

__global__ __launch_bounds__(256)
void final_reduce(float* __restrict__ out) {
    float s0 = 0.f, s1 = 0.f, s2 = 0.f, s3 = 0.f;
    for (int i = threadIdx.x; i < B_N; i += blockDim.x) {
        s0 += g_part[i * 4 + 0]; s1 += g_part[i * 4 + 1];
        s2 += g_part[i * 4 + 2]; s3 += g_part[i * 4 + 3];
    }
    s0 = blockSum(s0); s1 = blockSum(s1); s2 = blockSum(s2); s3 = blockSum(s3);
    if (threadIdx.x == 0) {
        out[0] = s0 / ((float)B_N * (float)D_N);
        out[1] = s1 / (float)B_N;
        out[2] = s2 / (float)B_N;
        out[3] = s3 / (float)B_N;
    }
}

// ---------------- launch ----------------
extern "C" void kernel_launch(void* const* d_in, const int* in_sizes, int n_in,
                              void* d_out, int out_size) {
    const float* gen = (const float*)d_in[0];
    const float* pos = (const float*)d_in[1];
    float* out = (float*)d_out;

    prep_kernel<<<2 * B_N, 256>>>(gen, pos);

    // Attraction: scores(gen,pos) full grid -> softmax -> W@pos - gen
    score_wmma<<<dim3(64, 64), 128>>>(0, 0);
    softmax_w16<<<B_N, 256>>>(0);
    wavg_wmma<<<dim3(8, 64), 128>>>(gen, 0);

    // Repulsion: scores(gen,gen) SYMMETRIC (upper-triangle tiles) -> softmax -> W@gen - gen
    score_wmma<<<dim3(64 * 65 / 2, 1), 128>>>(1, 1);
    softmax_w16<<<B_N, 256>>>(1);
    wavg_wmma<<<dim3(8, 64), 128>>>(gen, 1);

    row_reduce<<<B_N, 256>>>();
    final_reduce<<<1, 256>>>(out);
}

// round 17
// speedup vs baseline: 2.7743x; 1.7288x over previous
#include <cuda_runtime.h>
#include <cuda_fp16.h>
#include <cuda_pipeline.h>
#include <mma.h>
#include <math.h>
#include <stdint.h>

using namespace nvcuda;

// Problem constants (B=8192, B_pos=8192, D=1024, T=0.1)
#define B_N 8192
#define D_N 1024

// ---------------- scratch: 320 MB (== proven R2 footprint; < proven 384 MB cap) ----------------
// g_S doubles as fp32 score matrix, then per-row fp16 WH plane in place:
//   row r as halves: (half*)g_S + r*2*B_N ; [0..B_N)=WH
static __device__ __align__(256) float  g_S[(size_t)B_N * B_N];      // 256 MB
static __device__ __align__(256) __half g_genH[(size_t)B_N * D_N];   // 16 MB
static __device__ __align__(256) __half g_posH[(size_t)B_N * D_N];   // 16 MB
static __device__ __align__(256) float g_attr[(size_t)B_N * D_N];    // 32 MB
static __device__ __align__(256) float g_rep[(size_t)B_N * D_N];     // 32 MB (totals 352 MB w/ below)
static __device__ float g_gn[B_N];
static __device__ float g_pn[B_N];
static __device__ float g_part[B_N * 4];

// ---------------- reductions (proven) ----------------
__device__ __forceinline__ float warpSum(float v) {
#pragma unroll
    for (int o = 16; o > 0; o >>= 1) v += __shfl_xor_sync(0xffffffffu, v, o);
    return v;
}
__device__ __forceinline__ float warpMax(float v) {
#pragma unroll
    for (int o = 16; o > 0; o >>= 1) v = fmaxf(v, __shfl_xor_sync(0xffffffffu, v, o));
    return v;
}
__device__ float blockSum(float v) {
    __shared__ float s[33];
    int lane = threadIdx.x & 31, w = threadIdx.x >> 5;
    __syncthreads();
    v = warpSum(v);
    if (lane == 0) s[w] = v;
    __syncthreads();
    if (w == 0) {
        float t = (threadIdx.x < (blockDim.x >> 5)) ? s[threadIdx.x] : 0.f;
        t = warpSum(t);
        if (lane == 0) s[32] = t;
    }
    __syncthreads();
    return s[32];
}
__device__ float blockMax(float v) {
    __shared__ float s[33];
    int lane = threadIdx.x & 31, w = threadIdx.x >> 5;
    __syncthreads();
    v = warpMax(v);
    if (lane == 0) s[w] = v;
    __syncthreads();
    if (w == 0) {
        float t = (threadIdx.x < (blockDim.x >> 5)) ? s[threadIdx.x] : -INFINITY;
        t = warpMax(t);
        if (lane == 0) s[32] = t;
    }
    __syncthreads();
    return s[32];
}

// ---------------- K0: fused row norms + fp16 hi plane (lo planes no longer used) ----------------
__global__ __launch_bounds__(256)
void prep_kernel(const float* __restrict__ gen, const float* __restrict__ pos) {
    int row = blockIdx.x;
    const float* src; __half* H; float* dst;
    if (row < B_N) {
        src = gen + (size_t)row * D_N;
        H = g_genH + (size_t)row * D_N;
        dst = &g_gn[row];
    } else {
        int r = row - B_N;
        src = pos + (size_t)r * D_N;
        H = g_posH + (size_t)r * D_N;
        dst = &g_pn[r];
    }
    float s = 0.f;
    for (int c = threadIdx.x * 4; c < D_N; c += blockDim.x * 4) {
        float4 v = *(const float4*)(src + c);
        s += v.x * v.x + v.y * v.y + v.z * v.z + v.w * v.w;
        *(__half2*)(H + c)     = __halves2half2(__float2half(v.x), __float2half(v.y));
        *(__half2*)(H + c + 2) = __halves2half2(__float2half(v.z), __float2half(v.w));
    }
    s = blockSum(s);
    if (threadIdx.x == 0) *dst = s;
}

#define LDS32 40                   // padded smem stride in halves (32 + 8)
#define TILE32 (128 * LDS32)       // 5120 halves per operand tile
#define LDSP 136
#define WTILE (128 * LDS32)
#define PTILE (32 * LDSP)

// ---------------- K1: score GEMM -- SINGLE segment gH·pH ----------------
// (Logit jitter ~1.3e-3 absolute, zero-mean random across pairs; R16 measured zero output
//  impact from the comparable gL·pH term. dot is now exactly symmetric for gen x gen.)
__global__ __launch_bounds__(128)
void score_wmma(int b_is_gen, int sym) {
    __shared__ __align__(32) __half sh[4 * TILE32];   // 40,960 B
    const int tid = threadIdx.x, lane = tid & 31, wid = tid >> 5;
    const int wm = (wid & 1) * 64, wn = (wid >> 1) * 64;

    int bx, by;
    if (sym) {
        int t = blockIdx.x;
        bx = (int)((-1.0 + sqrt(1.0 + 8.0 * (double)t)) * 0.5);
        while ((bx + 1) * (bx + 2) / 2 <= t) bx++;
        while (bx * (bx + 1) / 2 > t) bx--;
        by = t - bx * (bx + 1) / 2;      // by <= bx
    } else {
        bx = blockIdx.x; by = blockIdx.y;
    }
    const int m0 = by * 128, n0 = bx * 128;

    const __half* A = g_genH;
    const __half* B = b_is_gen ? g_genH : g_posH;
    const int NTT = D_N / 32;            // 32 k-tiles

    auto issue = [&](int t, int s) {
        __half* dA = sh + s * 2 * TILE32;
        __half* dB = dA + TILE32;
#pragma unroll
        for (int i = 0; i < 4; i++) {
            int f = i * 128 + tid, r = f >> 2, c = f & 3;
            __pipeline_memcpy_async(dA + r * LDS32 + c * 8,
                                    A + (size_t)(m0 + r) * D_N + t * 32 + c * 8, 16);
            __pipeline_memcpy_async(dB + r * LDS32 + c * 8,
                                    B + (size_t)(n0 + r) * D_N + t * 32 + c * 8, 16);
        }
        __pipeline_commit();
    };

    wmma::fragment<wmma::accumulator, 16, 16, 16, float> cfr[4][4];
#pragma unroll
    for (int i = 0; i < 4; i++)
#pragma unroll
        for (int j = 0; j < 4; j++) wmma::fill_fragment(cfr[i][j], 0.f);

    issue(0, 0);
    for (int u = 0; u < NTT; u++) {
        if (u + 1 < NTT) { issue(u + 1, (u + 1) & 1); __pipeline_wait_prior(1); }
        else             { __pipeline_wait_prior(0); }
        __syncthreads();
        const __half* bufA = sh + (u & 1) * 2 * TILE32;
        const __half* bufB = bufA + TILE32;
#pragma unroll
        for (int ks = 0; ks < 2; ks++) {
            wmma::fragment<wmma::matrix_a, 16, 16, 16, __half, wmma::row_major> afr[4];
            wmma::fragment<wmma::matrix_b, 16, 16, 16, __half, wmma::col_major> bfr[4];
#pragma unroll
            for (int i = 0; i < 4; i++)
                wmma::load_matrix_sync(afr[i], bufA + (wm + i * 16) * LDS32 + ks * 16, LDS32);
#pragma unroll
            for (int j = 0; j < 4; j++)
                wmma::load_matrix_sync(bfr[j], bufB + (wn + j * 16) * LDS32 + ks * 16, LDS32);
#pragma unroll
            for (int i = 0; i < 4; i++)
#pragma unroll
                for (int j = 0; j < 4; j++)
                    wmma::mma_sync(cfr[i][j], afr[i], bfr[j], cfr[i][j]);
        }
        __syncthreads();
    }

    // epilogue: per 16x16 patch -> transform -> write (+ mirror in symmetric off-diag tiles)
    float* patch = ((float*)sh) + wid * 256;
    const float* bnp = b_is_gen ? g_gn : g_pn;
    const int do_mirror = sym && (bx != by);
#pragma unroll
    for (int i = 0; i < 4; i++) {
#pragma unroll
        for (int j = 0; j < 4; j++) {
            wmma::store_matrix_sync(patch, cfr[i][j], 16, wmma::mem_row_major);
            __syncwarp();
            const int pr = lane >> 1, pc = (lane & 1) * 8;
            {
                const int row = m0 + wm + i * 16 + pr;
                const int colb = n0 + wn + j * 16 + pc;
                const float an = g_gn[row];
                float4 bn0 = *(const float4*)(bnp + colb);
                float4 bn1 = *(const float4*)(bnp + colb + 4);
                const float* p = patch + pr * 16 + pc;
                float bns[8] = {bn0.x, bn0.y, bn0.z, bn0.w, bn1.x, bn1.y, bn1.z, bn1.w};
                float o[8];
#pragma unroll
                for (int e = 0; e < 8; e++) {
                    float d2 = fmaxf(an + bns[e] - 2.f * p[e], 0.f);
                    o[e] = -10.f * sqrtf(d2);
                }
                float* dst = g_S + (size_t)row * B_N + colb;
                *(float4*)dst       = make_float4(o[0], o[1], o[2], o[3]);
                *(float4*)(dst + 4) = make_float4(o[4], o[5], o[6], o[7]);
            }
            if (do_mirror) {
                const int mrow = n0 + wn + j * 16 + pr;
                const int mcolb = m0 + wm + i * 16 + pc;
                const float bnv = g_gn[mrow];
                float o[8];
#pragma unroll
                for (int e = 0; e < 8; e++) {
                    float an = g_gn[mcolb + e];
                    float d2 = fmaxf(an + bnv - 2.f * patch[(pc + e) * 16 + pr], 0.f);
                    o[e] = -10.f * sqrtf(d2);
                }
                float* dst = g_S + (size_t)mrow * B_N + mcolb;
                *(float4*)dst       = make_float4(o[0], o[1], o[2], o[3]);
                *(float4*)(dst + 4) = make_float4(o[4], o[5], o[6], o[7]);
            }
            __syncwarp();
        }
    }
}

// ---------------- K2: row softmax -> fp16 WH plane in place (proven) ----------------
__global__ __launch_bounds__(256)
void softmax_w16(int mask_diag) {
    __shared__ float sm[B_N];
    int row = blockIdx.x;
    const float* Srow = g_S + (size_t)row * B_N;
    float mx = -INFINITY;
    for (int j = threadIdx.x; j < B_N; j += blockDim.x) {
        float v = Srow[j];
        if (mask_diag && j == row) v = -INFINITY;
        sm[j] = v;
        mx = fmaxf(mx, v);
    }
    mx = blockMax(mx);
    float sum = 0.f;
    for (int j = threadIdx.x; j < B_N; j += blockDim.x) {
        float e = expf(sm[j] - mx);
        sm[j] = e;
        sum += e;
    }
    sum = blockSum(sum);
    float inv = 1.f / sum;
    __syncthreads();
    __half* WH = (__half*)g_S + (size_t)row * (2 * B_N);
    for (int j = threadIdx.x; j < B_N; j += blockDim.x)
        WH[j] = __float2half(sm[j] * inv);
}

// ---------------- K3: wavg GEMM (flipped, proven) -- SINGLE segment WH·PH ----------------
__global__ __launch_bounds__(128)
void wavg_wmma(const float* __restrict__ sub, int to_rep) {
    __shared__ __align__(32) __half shW[2 * WTILE];
    __shared__ __align__(32) __half shP[2 * PTILE];
    const int tid = threadIdx.x, lane = tid & 31, wid = tid >> 5;
    const int w_nn = (wid & 1) * 64;
    const int w_m  = (wid >> 1) * 64;
    const int n0 = blockIdx.x * 128;
    const int m0 = blockIdx.y * 128;

    const __half* Wp = (const __half*)g_S;           // WH plane, ld 2*B_N
    const __half* Pp = to_rep ? g_genH : g_posH;     // PH plane, ld D_N
    const int NTT = B_N / 32;                        // 256 k-tiles

    auto issue = [&](int t, int s) {
        __half* dW = shW + s * WTILE;
        __half* dP = shP + s * PTILE;
#pragma unroll
        for (int i = 0; i < 4; i++) {
            int f = i * 128 + tid;
            int rw = f >> 2, cw = f & 3;
            __pipeline_memcpy_async(dW + rw * LDS32 + cw * 8,
                                    Wp + (size_t)(m0 + rw) * (2 * B_N) + t * 32 + cw * 8, 16);
            int rp = f >> 4, cp = f & 15;
            __pipeline_memcpy_async(dP + rp * LDSP + cp * 8,
                                    Pp + (size_t)(t * 32 + rp) * D_N + n0 + cp * 8, 16);
        }
        __pipeline_commit();
    };

    wmma::fragment<wmma::accumulator, 16, 16, 16, float> cfr[4][4];   // [nn][m]
#pragma unroll
    for (int i = 0; i < 4; i++)
#pragma unroll
        for (int j = 0; j < 4; j++) wmma::fill_fragment(cfr[i][j], 0.f);

    issue(0, 0);
    for (int u = 0; u < NTT; u++) {
        if (u + 1 < NTT) { issue(u + 1, (u + 1) & 1); __pipeline_wait_prior(1); }
        else             { __pipeline_wait_prior(0); }
        __syncthreads();
        const __half* bufW = shW + (u & 1) * WTILE;
        const __half* bufP = shP + (u & 1) * PTILE;
#pragma unroll
        for (int ks = 0; ks < 2; ks++) {
            wmma::fragment<wmma::matrix_a, 16, 16, 16, __half, wmma::col_major> afr[4];
            wmma::fragment<wmma::matrix_b, 16, 16, 16, __half, wmma::col_major> bfr[4];
#pragma unroll
            for (int i = 0; i < 4; i++)
                wmma::load_matrix_sync(afr[i], bufP + (ks * 16) * LDSP + w_nn + i * 16, LDSP);
#pragma unroll
            for (int j = 0; j < 4; j++)
                wmma::load_matrix_sync(bfr[j], bufW + (w_m + j * 16) * LDS32 + ks * 16, LDS32);
#pragma unroll
            for (int i = 0; i < 4; i++)
#pragma unroll
                for (int j = 0; j < 4; j++)
                    wmma::mma_sync(cfr[i][j], afr[i], bfr[j], cfr[i][j]);
        }
        __syncthreads();
    }

    float* outp = to_rep ? g_rep : g_attr;
    float* patch = ((float*)shW) + wid * 256;
#pragma unroll
    for (int i = 0; i < 4; i++) {
#pragma unroll
        for (int j = 0; j < 4; j++) {
            wmma::store_matrix_sync(patch, cfr[i][j], 16, wmma::mem_col_major);
            __syncwarp();
            const int pr = lane >> 1, pc = (lane & 1) * 8;
            const int m  = m0 + w_m + j * 16 + pr;
            const int nn = n0 + w_nn + i * 16 + pc;
            const float* p = patch + pr * 16 + pc;
            size_t base = (size_t)m * D_N + nn;
            float4 s0 = *(const float4*)(sub + base);
            float4 s1 = *(const float4*)(sub + base + 4);
            *(float4*)(outp + base)     = make_float4(p[0] - s0.x, p[1] - s0.y,
                                                      p[2] - s0.z, p[3] - s0.w);
            *(float4*)(outp + base + 4) = make_float4(p[4] - s1.x, p[5] - s1.y,
                                                      p[6] - s1.z, p[7] - s1.w);
            __syncwarp();
        }
    }
}

// ---------------- K4/K5: final reductions (proven) ----------------
__global__ __launch_bounds__(256)
void row_reduce() {
    int row = blockIdx.x;
    const float* a = g_attr + (size_t)row * D_N;
    const float* r = g_rep + (size_t)row * D_N;
    float sa = 0.f, sr = 0.f, sd = 0.f;
    for (int c = threadIdx.x * 4; c < D_N; c += blockDim.x * 4) {
        float4 av = *(const float4*)(a + c);
        float4 rv = *(const float4*)(r + c);
        float dx = av.x - rv.x, dy = av.y - rv.y, dz = av.z - rv.z, dw = av.w - rv.w;
        sa += av.x * av.x + av.y * av.y + av.z * av.z + av.w * av.w;
        sr += rv.x * rv.x + rv.y * rv.y + rv.z * rv.z + rv.w * rv.w;
        sd += dx * dx + dy * dy + dz * dz + dw * dw;
    }
    sa = blockSum(sa); sr = blockSum(sr); sd = blockSum(sd);
    if (threadIdx.x == 0) {
        g_part[row * 4 + 0] = sd;
        g_part[row * 4 + 1] = sqrtf(sd);
        g_part[row * 4 + 2] = sqrtf(sa);
        g_part[row * 4 + 3] = sqrtf(sr);
    }
}

__global__ __launch_bounds__(256)
void final_reduce(float* __restrict__ out) {
    float s0 = 0.f, s1 = 0.f, s2 = 0.f, s3 = 0.f;
    for (int i = threadIdx.x; i < B_N; i += blockDim.x) {
        s0 += g_part[i * 4 + 0]; s1 += g_part[i * 4 + 1];
        s2 += g_part[i * 4 + 2]; s3 += g_part[i * 4 + 3];
    }
    s0 = blockSum(s0); s1 = blockSum(s1); s2 = blockSum(s2); s3 = blockSum(s3);
    if (threadIdx.x == 0) {
        out[0] = s0 / ((float)B_N * (float)D_N);
        out[1] = s1 / (float)B_N;
        out[2] = s2 / (float)B_N;
        out[3] = s3 / (float)B_N;
    }
}

// ---------------- launch ----------------
extern "C" void kernel_launch(void* const* d_in, const int* in_sizes, int n_in,
                              void* d_out, int out_size) {
    const float* gen = (const float*)d_in[0];
    const float* pos = (const float*)d_in[1];
    float* out = (float*)d_out;

    prep_kernel<<<2 * B_N, 256>>>(gen, pos);

    // Attraction: scores(gen,pos) full grid -> softmax -> W@pos - gen
    score_wmma<<<dim3(64, 64), 128>>>(0, 0);
    softmax_w16<<<B_N, 256>>>(0);
    wavg_wmma<<<dim3(8, 64), 128>>>(gen, 0);

    // Repulsion: scores(gen,gen) SYMMETRIC (upper-triangle tiles) -> softmax -> W@gen - gen
    score_wmma<<<dim3(64 * 65 / 2, 1), 128>>>(1, 1);
    softmax_w16<<<B_N, 256>>>(1);
    wavg_wmma<<<dim3(8, 64), 128>>>(gen, 1);

    row_reduce<<<B_N, 256>>>();
    final_reduce<<<1, 256>>>(out);
}